// round 5
// baseline (speedup 1.0000x reference)
#include <cuda_runtime.h>
#include <cstdint>

#define SQ   4096
#define BHN  64
#define PB   68      // plain smem pitch (floats) - FFMA2 kernels
#define P2   136     // interleaved hi/lo pitch (floats): 64 value-pairs + pad
#define NSPLIT 16    // kc blocks per bh (each block = 2 sub-splits)
#define NS2    32    // total softmax splits

typedef unsigned long long u64t;

// ---------------- scratch ----------------
__device__ float g_Qlm [BHN*64*64];   // landmark means of Q, *0.125 folded
__device__ float g_KlmT[BHN*64*64];   // landmark means of K, [d][lm]
__device__ float g_Klm [BHN*64*64];   // landmark means of K, [lm][d]
__device__ float g_Inv [BHN*64*64];   // Newton inverse
__device__ float g_W   [BHN*64*64];   // inv @ F : [m][d]
__device__ float g_pacc[(size_t)NS2*BHN*64*64];
__device__ float g_psum[NS2*BHN*64];

// ---------------- helpers ----------------
__device__ __forceinline__ u64t pk2(float lo, float hi) {
    u64t r; asm("mov.b64 %0, {%1, %2};" : "=l"(r) : "f"(lo), "f"(hi)); return r;
}
__device__ __forceinline__ u64t ffma2(u64t a, u64t b, u64t c) {
    u64t d; asm("fma.rn.f32x2 %0, %1, %2, %3;" : "=l"(d) : "l"(a), "l"(b), "l"(c)); return d;
}
__device__ __forceinline__ float tf32r(float x) {
    float r; asm("cvt.rna.tf32.f32 %0, %1;" : "=f"(r) : "f"(x)); return r;
}
__device__ __forceinline__ void mma8(float c[4], float a0, float a1, float a2, float a3,
                                     float b0, float b1) {
    asm volatile("mma.sync.aligned.m16n8k8.row.col.f32.tf32.tf32.f32 "
        "{%0,%1,%2,%3}, {%4,%5,%6,%7}, {%8,%9}, {%0,%1,%2,%3};"
        : "+f"(c[0]), "+f"(c[1]), "+f"(c[2]), "+f"(c[3])
        : "r"(__float_as_uint(a0)), "r"(__float_as_uint(a1)),
          "r"(__float_as_uint(a2)), "r"(__float_as_uint(a3)),
          "r"(__float_as_uint(b0)), "r"(__float_as_uint(b1)));
}
// split a float4 to hi/lo interleaved pairs and store 8 floats
__device__ __forceinline__ void st_hl4(float* dst, float4 v) {
    float4 p0, p1;
    p0.x = tf32r(v.x); p0.y = v.x - p0.x;
    p0.z = tf32r(v.y); p0.w = v.y - p0.z;
    p1.x = tf32r(v.z); p1.y = v.z - p1.x;
    p1.z = tf32r(v.w); p1.w = v.w - p1.z;
    *(float4*)(dst)     = p0;
    *(float4*)(dst + 4) = p1;
}
// warp tile: C[16x64] += A[16x64] * B  (3xTF32, interleaved hi/lo operands)
// BN=true : B indexed [n][k]   (row = n)
// BN=false: B indexed [k][n]   (row = k)
template<bool BN>
__device__ __forceinline__ void mma_16x64(const float* __restrict__ Ai, int rA, int rB,
                                          const float* __restrict__ Bi,
                                          int g, int t, float c[8][4]) {
#pragma unroll
    for (int kt = 0; kt < 8; kt++) {
        int k0 = kt*8;
        float2 aA0 = *(const float2*)(Ai + rA*P2 + 2*(k0+t));
        float2 aB0 = *(const float2*)(Ai + rB*P2 + 2*(k0+t));
        float2 aA1 = *(const float2*)(Ai + rA*P2 + 2*(k0+t+4));
        float2 aB1 = *(const float2*)(Ai + rB*P2 + 2*(k0+t+4));
#pragma unroll
        for (int nt = 0; nt < 8; nt++) {
            int n0 = nt*8;
            float2 b0, b1;
            if (BN) {
                b0 = *(const float2*)(Bi + (n0+g)*P2 + 2*(k0+t));
                b1 = *(const float2*)(Bi + (n0+g)*P2 + 2*(k0+t+4));
            } else {
                b0 = *(const float2*)(Bi + (k0+t)*P2 + 2*(n0+g));
                b1 = *(const float2*)(Bi + (k0+t+4)*P2 + 2*(n0+g));
            }
            mma8(c[nt], aA0.x, aB0.x, aA1.x, aB1.x, b0.x, b1.x);  // ah*bh
            mma8(c[nt], aA0.y, aB0.y, aA1.y, aB1.y, b0.x, b1.x);  // al*bh
            mma8(c[nt], aA0.x, aB0.x, aA1.x, aB1.x, b0.y, b1.y);  // ah*bl
        }
    }
}

// ---------------- plain FFMA2 64x64 matmul (newton / reduce) ----------------
__device__ __forceinline__ void mm64_core(const float* __restrict__ A,
                                          const float* __restrict__ B,
                                          int rq, int cq, u64t acc[4][2]) {
#pragma unroll
    for (int k = 0; k < 64; k++) {
        u64t b0 = *(const u64t*)(B + k*PB + 2*cq);
        u64t b1 = *(const u64t*)(B + k*PB + 2*cq + 32);
#pragma unroll
        for (int r = 0; r < 4; r++) {
            float a = A[(rq + 16*r)*PB + k];
            u64t a2 = pk2(a, a);
            acc[r][0] = ffma2(a2, b0, acc[r][0]);
            acc[r][1] = ffma2(a2, b1, acc[r][1]);
        }
    }
}
__device__ __noinline__ void mm64_smem(const float* __restrict__ A,
                                       const float* __restrict__ B,
                                       float* __restrict__ C, int tid) {
    int cq = tid & 15, rq = tid >> 4;
    u64t acc[4][2] = {};
    mm64_core(A, B, rq, cq, acc);
#pragma unroll
    for (int r = 0; r < 4; r++) {
        *(u64t*)(C + (rq+16*r)*PB + 2*cq)      = acc[r][0];
        *(u64t*)(C + (rq+16*r)*PB + 2*cq + 32) = acc[r][1];
    }
}

// ---------------- pooling ----------------
__global__ void __launch_bounds__(256) pool_kernel(const float* __restrict__ Q,
                                                   const float* __restrict__ K) {
    int bh = blockIdx.x >> 6, lm = blockIdx.x & 63;
    int d = threadIdx.x & 63, rg = threadIdx.x >> 6;
    const float* qb = Q + ((size_t)bh*SQ + lm*64)*64 + d;
    const float* kb = K + ((size_t)bh*SQ + lm*64)*64 + d;
    float sq = 0.f, sk = 0.f;
    for (int r = rg; r < 64; r += 4) { sq += qb[(size_t)r*64]; sk += kb[(size_t)r*64]; }
    __shared__ float shq[256], shk[256];
    shq[threadIdx.x] = sq; shk[threadIdx.x] = sk;
    __syncthreads();
    if (rg == 0) {
        float q = (shq[d] + shq[64+d] + shq[128+d] + shq[192+d]) * (1.0f/512.0f); // mean*0.125
        float k = (shk[d] + shk[64+d] + shk[128+d] + shk[192+d]) * (1.0f/64.0f);
        g_Qlm [bh*4096 + lm*64 + d] = q;
        g_Klm [bh*4096 + lm*64 + d] = k;
        g_KlmT[bh*4096 + d*64 + lm] = k;
    }
}

// ---------------- Newton-Schulz body (FFMA2; latency-hidden) ----------------
__device__ void newton_body(float* sm, int bh) {
    float* A  = sm;
    float* Vb = sm + 1*64*PB;
    float* P  = sm + 2*64*PB;
    float* T  = sm + 3*64*PB;
    float* U  = sm + 4*64*PB;
    __shared__ float nsred[256], nsrow[64], nscol[64], nscale[1];
    int tid = threadIdx.x;

    for (int idx = tid; idx < 4096; idx += 256) {
        int i = idx >> 6, k = idx & 63;
        T[i*PB + k] = g_Qlm[bh*4096 + idx];
        U[i*PB + k] = g_KlmT[bh*4096 + idx];
    }
    __syncthreads();
    mm64_smem(T, U, A, tid);
    __syncthreads();
    {
        int q = tid & 3, r = tid >> 2;
        float* Lr = A + r*PB + q*16;
        float mt = Lr[0];
#pragma unroll
        for (int c = 1; c < 16; c++) mt = fmaxf(mt, Lr[c]);
        nsred[tid] = mt; __syncthreads();
        float m = fmaxf(fmaxf(nsred[r*4], nsred[r*4+1]), fmaxf(nsred[r*4+2], nsred[r*4+3]));
        float ps = 0.f;
#pragma unroll
        for (int c = 0; c < 16; c++) { float e = __expf(Lr[c] - m); Lr[c] = e; ps += e; }
        __syncthreads();
        nsred[tid] = ps; __syncthreads();
        float inv = 1.0f / (nsred[r*4] + nsred[r*4+1] + nsred[r*4+2] + nsred[r*4+3]);
#pragma unroll
        for (int c = 0; c < 16; c++) Lr[c] *= inv;
    }
    __syncthreads();
    if (tid < 64)       { float s = 0.f; for (int j = 0; j < 64; j++) s += A[tid*PB + j]; nsrow[tid] = s; }
    else if (tid < 128) { int c = tid - 64; float s = 0.f; for (int i = 0; i < 64; i++) s += A[i*PB + c]; nscol[c] = s; }
    __syncthreads();
    if (tid == 0) {
        float mr = nsrow[0], mc = nscol[0];
        for (int i = 1; i < 64; i++) { mr = fmaxf(mr, nsrow[i]); mc = fmaxf(mc, nscol[i]); }
        nscale[0] = 1.0f / (mr * mc);
    }
    __syncthreads();
    float sc = nscale[0];
    for (int idx = tid; idx < 4096; idx += 256) {
        int i = idx >> 6, j = idx & 63;
        Vb[j*PB + i] = A[i*PB + j] * sc;
    }
    __syncthreads();
#pragma unroll 1
    for (int it = 0; it < 6; it++) {
        mm64_smem(A, Vb, P, tid); __syncthreads();
        for (int idx = tid; idx < 4096; idx += 256) {
            int i = idx >> 6, j = idx & 63;
            T[i*PB + j] = (i == j ? 7.0f : 0.0f) - P[i*PB + j];
        }
        __syncthreads();
        mm64_smem(P, T, U, tid); __syncthreads();
        for (int idx = tid; idx < 4096; idx += 256) {
            int i = idx >> 6, j = idx & 63;
            T[i*PB + j] = (i == j ? 15.0f : 0.0f) - U[i*PB + j];
        }
        __syncthreads();
        mm64_smem(P, T, U, tid); __syncthreads();
        for (int idx = tid; idx < 4096; idx += 256) {
            int i = idx >> 6, j = idx & 63;
            T[i*PB + j] = (i == j ? 3.25f : 0.0f) - 0.25f * U[i*PB + j];
        }
        __syncthreads();
        mm64_smem(Vb, T, U, tid); __syncthreads();
        float* tmp = Vb; Vb = U; U = tmp;
    }
    for (int idx = tid; idx < 4096; idx += 256) {
        int i = idx >> 6, j = idx & 63;
        g_Inv[bh*4096 + idx] = Vb[i*PB + j];
    }
}

// ---------------- kc body: mma tf32, split softmax (no max; logits ~ +-1) ----------------
__device__ void kc_body_mma(const float* __restrict__ K, const float* __restrict__ V,
                            float* sm, int sp, int bh) {
    float* Qi = sm;                                 // 64*P2, shared by both wgs
    int tid = threadIdx.x;
    int wg = tid >> 7, wtid = tid & 127;
    int w = wtid >> 5, lane = tid & 31;
    int g = lane >> 2, t = lane & 3;
    float* KPi = sm + 64*P2 + wg*(2*64*P2);         // K tile, later P
    float* Vi  = KPi + 64*P2;

    // load Qlm (already *0.125) hi/lo interleaved
#pragma unroll
    for (int it = 0; it < 4; it++) {
        int f4 = it*256 + tid;
        int r = f4 >> 4, c4 = (f4 & 15) << 2;
        st_hl4(Qi + r*P2 + 2*c4, *(const float4*)(g_Qlm + bh*4096 + f4*4));
    }
    __syncthreads();

    float acc[8][4];
#pragma unroll
    for (int n = 0; n < 8; n++) { acc[n][0]=0.f; acc[n][1]=0.f; acc[n][2]=0.f; acc[n][3]=0.f; }
    float rsA = 0.f, rsB = 0.f;
    int rA = w*16 + g, rB = rA + 8;

#pragma unroll 1
    for (int t2 = 0; t2 < 2; t2++) {
        int s0 = sp*256 + wg*128 + t2*64;
        // load K,V tiles (64x64 each) hi/lo interleaved
#pragma unroll
        for (int it = 0; it < 8; it++) {
            int f4 = it*128 + wtid;
            int r = f4 >> 4, c4 = (f4 & 15) << 2;
            st_hl4(KPi + r*P2 + 2*c4, *(const float4*)(K + ((size_t)bh*SQ + s0 + r)*64 + c4));
            st_hl4(Vi  + r*P2 + 2*c4, *(const float4*)(V + ((size_t)bh*SQ + s0 + r)*64 + c4));
        }
        asm volatile("bar.sync %0, %1;" :: "r"(wg+1), "r"(128) : "memory");

        // logits = Qlm @ Ktile^T   (B row = n = s)
        float c[8][4];
#pragma unroll
        for (int n = 0; n < 8; n++) { c[n][0]=0.f; c[n][1]=0.f; c[n][2]=0.f; c[n][3]=0.f; }
        mma_16x64<true>(Qi, rA, rB, KPi, g, t, c);

        // exp (no max shift: |logit| < ~1) + row sums
        float sA = 0.f, sB = 0.f;
#pragma unroll
        for (int n = 0; n < 8; n++) {
            c[n][0] = __expf(c[n][0]); c[n][1] = __expf(c[n][1]);
            c[n][2] = __expf(c[n][2]); c[n][3] = __expf(c[n][3]);
            sA += c[n][0] + c[n][1];
            sB += c[n][2] + c[n][3];
        }
        sA += __shfl_xor_sync(0xffffffffu, sA, 1);
        sA += __shfl_xor_sync(0xffffffffu, sA, 2);
        sB += __shfl_xor_sync(0xffffffffu, sB, 1);
        sB += __shfl_xor_sync(0xffffffffu, sB, 2);
        rsA += sA; rsB += sB;

        asm volatile("bar.sync %0, %1;" :: "r"(wg+1), "r"(128) : "memory");
        // store P hi/lo into K buffer (warp-local rows)
#pragma unroll
        for (int n = 0; n < 8; n++) {
            int col = n*8 + 2*t;
            float h0 = tf32r(c[n][0]), h1 = tf32r(c[n][1]);
            float h2 = tf32r(c[n][2]), h3 = tf32r(c[n][3]);
            float4 p0 = {h0, c[n][0]-h0, h1, c[n][1]-h1};
            float4 p1 = {h2, c[n][2]-h2, h3, c[n][3]-h3};
            *(float4*)(KPi + rA*P2 + 2*col) = p0;
            *(float4*)(KPi + rB*P2 + 2*col) = p1;
        }
        __syncwarp();
        // acc += P @ Vtile   (B row = k = s)
        mma_16x64<false>(KPi, rA, rB, Vi, g, t, acc);
        asm volatile("bar.sync %0, %1;" :: "r"(wg+1), "r"(128) : "memory");
    }

    // epilogue: unnormalized partials + row sums
    int osp = sp*2 + wg;
    size_t base = ((size_t)osp*BHN + bh)*4096;
#pragma unroll
    for (int n = 0; n < 8; n++) {
        int col = n*8 + 2*t;
        float2 oA = {acc[n][0], acc[n][1]};
        float2 oB = {acc[n][2], acc[n][3]};
        *(float2*)(g_pacc + base + rA*64 + col) = oA;
        *(float2*)(g_pacc + base + rB*64 + col) = oB;
    }
    if (t == 0) {
        g_psum[(osp*BHN+bh)*64 + rA] = rsA;
        g_psum[(osp*BHN+bh)*64 + rB] = rsB;
    }
}

__global__ void __launch_bounds__(256, 1) mega_kernel(const float* __restrict__ K,
                                                      const float* __restrict__ V) {
    extern __shared__ __align__(16) float smg[];
    if (blockIdx.x < 64) newton_body(smg, blockIdx.x);
    else { int id = blockIdx.x - 64; kc_body_mma(K, V, smg, id & (NSPLIT-1), id >> 4); }
}

// ---------------- reduce splits -> F, W = Inv@F ----------------
__global__ void __launch_bounds__(256) reduce_winv_kernel() {
    extern __shared__ __align__(16) float smr[];
    float* Fs = smr;
    float* Iv = smr + 64*PB;
    int bh = blockIdx.x, tid = threadIdx.x;

    for (int idx = tid; idx < 4096; idx += 256)
        Iv[(idx>>6)*PB + (idx&63)] = g_Inv[bh*4096 + idx];

    int d = tid & 63, ig = tid >> 6;
    for (int i = ig; i < 64; i += 4) {
        float tot = 0.f;
#pragma unroll
        for (int s = 0; s < NS2; s++) tot += g_psum[(s*BHN+bh)*64 + i];
        float v = 0.f;
#pragma unroll
        for (int s = 0; s < NS2; s++)
            v += g_pacc[((size_t)s*BHN+bh)*4096 + i*64 + d];
        Fs[i*PB + d] = v / tot;
    }
    __syncthreads();
    int cq = tid & 15, rq = tid >> 4;
    u64t acc[4][2] = {};
    mm64_core(Iv, Fs, rq, cq, acc);
#pragma unroll
    for (int rr = 0; rr < 4; rr++) {
        *(u64t*)(g_W + (size_t)bh*4096 + (rq+16*rr)*64 + 2*cq)      = acc[rr][0];
        *(u64t*)(g_W + (size_t)bh*4096 + (rq+16*rr)*64 + 2*cq + 32) = acc[rr][1];
    }
}

// ---------------- kd: mma tf32, X = softmax(0.125 Q Klm^T) @ W ----------------
__global__ void __launch_bounds__(256, 1) kd_mma(const float* __restrict__ Q,
                                                 float* __restrict__ X) {
    extern __shared__ __align__(16) float sk[];
    float* Qi = sk;              // 128 x P2 (later P)
    float* Ki = Qi + 128*P2;     // 64 x P2
    float* Wi = Ki + 64*P2;      // 64 x P2
    int tid = threadIdx.x, lane = tid & 31, wid = tid >> 5;
    int g = lane >> 2, t = lane & 3;
    int tile = blockIdx.x, bh = blockIdx.y;

    const float* q0 = Q + ((size_t)bh*SQ + tile*128)*64;
#pragma unroll
    for (int it = 0; it < 8; it++) {
        int f4 = it*256 + tid;
        int r = f4 >> 4, c4 = (f4 & 15) << 2;
        float4 v = *(const float4*)(q0 + r*64 + c4);
        v.x *= 0.125f; v.y *= 0.125f; v.z *= 0.125f; v.w *= 0.125f;
        st_hl4(Qi + r*P2 + 2*c4, v);
    }
    const float* kl0 = g_Klm + (size_t)bh*4096;
    const float* w0  = g_W   + (size_t)bh*4096;
#pragma unroll
    for (int it = 0; it < 4; it++) {
        int f4 = it*256 + tid;
        int r = f4 >> 4, c4 = (f4 & 15) << 2;
        st_hl4(Ki + r*P2 + 2*c4, *(const float4*)(kl0 + r*64 + c4));
        st_hl4(Wi + r*P2 + 2*c4, *(const float4*)(w0  + r*64 + c4));
    }
    __syncthreads();

    int rA = wid*16 + g, rB = rA + 8;
    float c[8][4];
#pragma unroll
    for (int n = 0; n < 8; n++) { c[n][0]=0.f; c[n][1]=0.f; c[n][2]=0.f; c[n][3]=0.f; }

    // logits = Qs @ Klm^T   (B row = n)
    mma_16x64<true>(Qi, rA, rB, Ki, g, t, c);

    // softmax
    float mA = -1e30f, mB = -1e30f;
#pragma unroll
    for (int n = 0; n < 8; n++) {
        mA = fmaxf(mA, fmaxf(c[n][0], c[n][1]));
        mB = fmaxf(mB, fmaxf(c[n][2], c[n][3]));
    }
    mA = fmaxf(mA, __shfl_xor_sync(0xffffffffu, mA, 1));
    mA = fmaxf(mA, __shfl_xor_sync(0xffffffffu, mA, 2));
    mB = fmaxf(mB, __shfl_xor_sync(0xffffffffu, mB, 1));
    mB = fmaxf(mB, __shfl_xor_sync(0xffffffffu, mB, 2));
    float sA = 0.f, sB = 0.f;
#pragma unroll
    for (int n = 0; n < 8; n++) {
        c[n][0] = __expf(c[n][0] - mA); c[n][1] = __expf(c[n][1] - mA);
        c[n][2] = __expf(c[n][2] - mB); c[n][3] = __expf(c[n][3] - mB);
        sA += c[n][0] + c[n][1];
        sB += c[n][2] + c[n][3];
    }
    sA += __shfl_xor_sync(0xffffffffu, sA, 1);
    sA += __shfl_xor_sync(0xffffffffu, sA, 2);
    sB += __shfl_xor_sync(0xffffffffu, sB, 1);
    sB += __shfl_xor_sync(0xffffffffu, sB, 2);
    float rinvA = 1.0f / sA, rinvB = 1.0f / sB;

    // P into Qi (warp-local rows)
#pragma unroll
    for (int n = 0; n < 8; n++) {
        int col = n*8 + 2*t;
        float h0 = tf32r(c[n][0]), h1 = tf32r(c[n][1]);
        float h2 = tf32r(c[n][2]), h3 = tf32r(c[n][3]);
        float4 p0 = {h0, c[n][0]-h0, h1, c[n][1]-h1};
        float4 p1 = {h2, c[n][2]-h2, h3, c[n][3]-h3};
        *(float4*)(Qi + rA*P2 + 2*col) = p0;
        *(float4*)(Qi + rB*P2 + 2*col) = p1;
    }
    __syncwarp();

    // X~ = P @ W   (B row = k)
#pragma unroll
    for (int n = 0; n < 8; n++) { c[n][0]=0.f; c[n][1]=0.f; c[n][2]=0.f; c[n][3]=0.f; }
    mma_16x64<false>(Qi, rA, rB, Wi, g, t, c);

    float* x0 = X + ((size_t)bh*SQ + tile*128)*64;
#pragma unroll
    for (int n = 0; n < 8; n++) {
        int col = n*8 + 2*t;
        float2 o0 = {c[n][0]*rinvA, c[n][1]*rinvA};
        float2 o1 = {c[n][2]*rinvB, c[n][3]*rinvB};
        *(float2*)(x0 + rA*64 + col) = o0;
        *(float2*)(x0 + rB*64 + col) = o1;
    }
}

// ---------------- launcher ----------------
extern "C" void kernel_launch(void* const* d_in, const int* in_sizes, int n_in,
                              void* d_out, int out_size) {
    (void)in_sizes; (void)n_in; (void)out_size;
    const float* Q = (const float*)d_in[0];
    const float* K = (const float*)d_in[1];
    const float* V = (const float*)d_in[2];
    float* X = (float*)d_out;

    const int SMEM_MEGA = 5*64*P2*4;                 // 174080 (kc); newton needs 87040
    const int SMEM_RW   = 2*64*PB*4;                 // 34816
    const int SMEM_KD   = (128*P2 + 2*64*P2)*4;      // 139264
    cudaFuncSetAttribute(mega_kernel,        cudaFuncAttributeMaxDynamicSharedMemorySize, SMEM_MEGA);
    cudaFuncSetAttribute(reduce_winv_kernel, cudaFuncAttributeMaxDynamicSharedMemorySize, SMEM_RW);
    cudaFuncSetAttribute(kd_mma,             cudaFuncAttributeMaxDynamicSharedMemorySize, SMEM_KD);

    pool_kernel<<<BHN*64, 256>>>(Q, K);
    mega_kernel<<<64 + NSPLIT*BHN, 256, SMEM_MEGA>>>(K, V);
    reduce_winv_kernel<<<BHN, 256, SMEM_RW>>>();
    kd_mma<<<dim3(32, BHN), 256, SMEM_KD>>>(Q, X);
}

// round 6
// speedup vs baseline: 1.0817x; 1.0817x over previous
#include <cuda_runtime.h>
#include <cstdint>

#define SQ   4096
#define BHN  64
#define PB   68      // smem pitch (floats); 68 mod 32 = 4 -> conflict-free fragments
#define NSPLIT 16    // kc blocks per bh (each block = 2 sub-splits)
#define NS2    32    // total softmax splits

typedef unsigned long long u64t;

// ---------------- scratch ----------------
__device__ float g_Qlm [BHN*64*64];   // landmark means of Q, *0.125 folded
__device__ float g_KlmT[BHN*64*64];   // landmark means of K, [d][lm]
__device__ float g_Klm [BHN*64*64];   // landmark means of K, [lm][d]
__device__ float g_Inv [BHN*64*64];   // Newton inverse
__device__ float g_W   [BHN*64*64];   // inv @ F : [m][d]
__device__ float g_pacc[(size_t)NS2*BHN*64*64];
__device__ float g_psum[NS2*BHN*64];

// ---------------- helpers ----------------
__device__ __forceinline__ u64t pk2(float lo, float hi) {
    u64t r; asm("mov.b64 %0, {%1, %2};" : "=l"(r) : "f"(lo), "f"(hi)); return r;
}
__device__ __forceinline__ u64t ffma2(u64t a, u64t b, u64t c) {
    u64t d; asm("fma.rn.f32x2 %0, %1, %2, %3;" : "=l"(d) : "l"(a), "l"(b), "l"(c)); return d;
}
__device__ __forceinline__ float tf32r(float x) {
    float r; asm("cvt.rna.tf32.f32 %0, %1;" : "=f"(r) : "f"(x)); return r;
}
__device__ __forceinline__ void mma8(float c[4], float a0, float a1, float a2, float a3,
                                     float b0, float b1) {
    asm volatile("mma.sync.aligned.m16n8k8.row.col.f32.tf32.tf32.f32 "
        "{%0,%1,%2,%3}, {%4,%5,%6,%7}, {%8,%9}, {%0,%1,%2,%3};"
        : "+f"(c[0]), "+f"(c[1]), "+f"(c[2]), "+f"(c[3])
        : "r"(__float_as_uint(a0)), "r"(__float_as_uint(a1)),
          "r"(__float_as_uint(a2)), "r"(__float_as_uint(a3)),
          "r"(__float_as_uint(b0)), "r"(__float_as_uint(b1)));
}
// split float4 into hi/lo float4s, store to separate arrays
__device__ __forceinline__ void st_hl_sep(float* dh, float* dl, float4 v) {
    float4 h, l;
    h.x = tf32r(v.x); l.x = v.x - h.x;
    h.y = tf32r(v.y); l.y = v.y - h.y;
    h.z = tf32r(v.z); l.z = v.z - h.z;
    h.w = tf32r(v.w); l.w = v.w - h.w;
    *(float4*)dh = h;
    *(float4*)dl = l;
}
// warp tile: C[16x64] += A[16x64] * B (3xTF32, separate hi/lo arrays, pitch PB)
// BN=true : B indexed [n][k];  BN=false: B indexed [k][n]
template<bool BN>
__device__ __forceinline__ void mma_16x64(const float* __restrict__ Ah,
                                          const float* __restrict__ Al,
                                          int rA, int rB,
                                          const float* __restrict__ Bh,
                                          const float* __restrict__ Bl,
                                          int g, int t, float c[8][4]) {
#pragma unroll
    for (int kt = 0; kt < 8; kt++) {
        int k0 = kt*8;
        float ah0 = Ah[rA*PB + k0 + t],     ah1 = Ah[rB*PB + k0 + t];
        float ah2 = Ah[rA*PB + k0 + t + 4], ah3 = Ah[rB*PB + k0 + t + 4];
        float al0 = Al[rA*PB + k0 + t],     al1 = Al[rB*PB + k0 + t];
        float al2 = Al[rA*PB + k0 + t + 4], al3 = Al[rB*PB + k0 + t + 4];
#pragma unroll
        for (int nt = 0; nt < 8; nt++) {
            int n0 = nt*8;
            float bh0, bh1, bl0, bl1;
            if (BN) {
                bh0 = Bh[(n0+g)*PB + k0 + t]; bh1 = Bh[(n0+g)*PB + k0 + t + 4];
                bl0 = Bl[(n0+g)*PB + k0 + t]; bl1 = Bl[(n0+g)*PB + k0 + t + 4];
            } else {
                bh0 = Bh[(k0+t)*PB + n0 + g]; bh1 = Bh[(k0+t+4)*PB + n0 + g];
                bl0 = Bl[(k0+t)*PB + n0 + g]; bl1 = Bl[(k0+t+4)*PB + n0 + g];
            }
            mma8(c[nt], ah0, ah1, ah2, ah3, bh0, bh1);
            mma8(c[nt], al0, al1, al2, al3, bh0, bh1);
            mma8(c[nt], ah0, ah1, ah2, ah3, bl0, bl1);
        }
    }
}

// ---------------- plain FFMA2 64x64 matmul (newton / reduce) ----------------
__device__ __forceinline__ void mm64_core(const float* __restrict__ A,
                                          const float* __restrict__ B,
                                          int rq, int cq, u64t acc[4][2]) {
#pragma unroll
    for (int k = 0; k < 64; k++) {
        u64t b0 = *(const u64t*)(B + k*PB + 2*cq);
        u64t b1 = *(const u64t*)(B + k*PB + 2*cq + 32);
#pragma unroll
        for (int r = 0; r < 4; r++) {
            float a = A[(rq + 16*r)*PB + k];
            u64t a2 = pk2(a, a);
            acc[r][0] = ffma2(a2, b0, acc[r][0]);
            acc[r][1] = ffma2(a2, b1, acc[r][1]);
        }
    }
}
__device__ __noinline__ void mm64_smem(const float* __restrict__ A,
                                       const float* __restrict__ B,
                                       float* __restrict__ C, int tid) {
    int cq = tid & 15, rq = tid >> 4;
    u64t acc[4][2] = {};
    mm64_core(A, B, rq, cq, acc);
#pragma unroll
    for (int r = 0; r < 4; r++) {
        *(u64t*)(C + (rq+16*r)*PB + 2*cq)      = acc[r][0];
        *(u64t*)(C + (rq+16*r)*PB + 2*cq + 32) = acc[r][1];
    }
}

// ---------------- pooling ----------------
__global__ void __launch_bounds__(256) pool_kernel(const float* __restrict__ Q,
                                                   const float* __restrict__ K) {
    int bh = blockIdx.x >> 6, lm = blockIdx.x & 63;
    int d = threadIdx.x & 63, rg = threadIdx.x >> 6;
    const float* qb = Q + ((size_t)bh*SQ + lm*64)*64 + d;
    const float* kb = K + ((size_t)bh*SQ + lm*64)*64 + d;
    float sq = 0.f, sk = 0.f;
    for (int r = rg; r < 64; r += 4) { sq += qb[(size_t)r*64]; sk += kb[(size_t)r*64]; }
    __shared__ float shq[256], shk[256];
    shq[threadIdx.x] = sq; shk[threadIdx.x] = sk;
    __syncthreads();
    if (rg == 0) {
        float q = (shq[d] + shq[64+d] + shq[128+d] + shq[192+d]) * (1.0f/512.0f); // mean*0.125
        float k = (shk[d] + shk[64+d] + shk[128+d] + shk[192+d]) * (1.0f/64.0f);
        g_Qlm [bh*4096 + lm*64 + d] = q;
        g_Klm [bh*4096 + lm*64 + d] = k;
        g_KlmT[bh*4096 + d*64 + lm] = k;
    }
}

// ---------------- Newton-Schulz body (FFMA2; latency-hidden in mega) ----------------
__device__ void newton_body(float* sm, int bh) {
    float* A  = sm;
    float* Vb = sm + 1*64*PB;
    float* P  = sm + 2*64*PB;
    float* T  = sm + 3*64*PB;
    float* U  = sm + 4*64*PB;
    __shared__ float nsred[256], nsrow[64], nscol[64], nscale[1];
    int tid = threadIdx.x;

    for (int idx = tid; idx < 4096; idx += 256) {
        int i = idx >> 6, k = idx & 63;
        T[i*PB + k] = g_Qlm[bh*4096 + idx];
        U[i*PB + k] = g_KlmT[bh*4096 + idx];
    }
    __syncthreads();
    mm64_smem(T, U, A, tid);
    __syncthreads();
    {
        int q = tid & 3, r = tid >> 2;
        float* Lr = A + r*PB + q*16;
        float mt = Lr[0];
#pragma unroll
        for (int c = 1; c < 16; c++) mt = fmaxf(mt, Lr[c]);
        nsred[tid] = mt; __syncthreads();
        float m = fmaxf(fmaxf(nsred[r*4], nsred[r*4+1]), fmaxf(nsred[r*4+2], nsred[r*4+3]));
        float ps = 0.f;
#pragma unroll
        for (int c = 0; c < 16; c++) { float e = __expf(Lr[c] - m); Lr[c] = e; ps += e; }
        __syncthreads();
        nsred[tid] = ps; __syncthreads();
        float inv = 1.0f / (nsred[r*4] + nsred[r*4+1] + nsred[r*4+2] + nsred[r*4+3]);
#pragma unroll
        for (int c = 0; c < 16; c++) Lr[c] *= inv;
    }
    __syncthreads();
    if (tid < 64)       { float s = 0.f; for (int j = 0; j < 64; j++) s += A[tid*PB + j]; nsrow[tid] = s; }
    else if (tid < 128) { int c = tid - 64; float s = 0.f; for (int i = 0; i < 64; i++) s += A[i*PB + c]; nscol[c] = s; }
    __syncthreads();
    if (tid == 0) {
        float mr = nsrow[0], mc = nscol[0];
        for (int i = 1; i < 64; i++) { mr = fmaxf(mr, nsrow[i]); mc = fmaxf(mc, nscol[i]); }
        nscale[0] = 1.0f / (mr * mc);
    }
    __syncthreads();
    float sc = nscale[0];
    for (int idx = tid; idx < 4096; idx += 256) {
        int i = idx >> 6, j = idx & 63;
        Vb[j*PB + i] = A[i*PB + j] * sc;
    }
    __syncthreads();
#pragma unroll 1
    for (int it = 0; it < 6; it++) {
        mm64_smem(A, Vb, P, tid); __syncthreads();
        for (int idx = tid; idx < 4096; idx += 256) {
            int i = idx >> 6, j = idx & 63;
            T[i*PB + j] = (i == j ? 7.0f : 0.0f) - P[i*PB + j];
        }
        __syncthreads();
        mm64_smem(P, T, U, tid); __syncthreads();
        for (int idx = tid; idx < 4096; idx += 256) {
            int i = idx >> 6, j = idx & 63;
            T[i*PB + j] = (i == j ? 15.0f : 0.0f) - U[i*PB + j];
        }
        __syncthreads();
        mm64_smem(P, T, U, tid); __syncthreads();
        for (int idx = tid; idx < 4096; idx += 256) {
            int i = idx >> 6, j = idx & 63;
            T[i*PB + j] = (i == j ? 3.25f : 0.0f) - 0.25f * U[i*PB + j];
        }
        __syncthreads();
        mm64_smem(Vb, T, U, tid); __syncthreads();
        float* tmp = Vb; Vb = U; U = tmp;
    }
    for (int idx = tid; idx < 4096; idx += 256) {
        int i = idx >> 6, j = idx & 63;
        g_Inv[bh*4096 + idx] = Vb[i*PB + j];
    }
}

// ---------------- kc body: mma tf32, split softmax, no-max exp ----------------
__device__ void kc_body_mma(const float* __restrict__ K, const float* __restrict__ V,
                            float* sm, int sp, int bh) {
    float* Qh = sm;                  // 64*PB (shared by both wgs)
    float* Ql = Qh + 64*PB;
    int tid = threadIdx.x;
    int wg = tid >> 7, wtid = tid & 127;
    int w = wtid >> 5, lane = tid & 31;
    int g = lane >> 2, t = lane & 3;
    float* Kh = Ql + 64*PB + wg*(4*64*PB);   // later P hi
    float* Kl = Kh + 64*PB;                  // later P lo
    float* Vh = Kl + 64*PB;
    float* Vl = Vh + 64*PB;

    // load Qlm (already *0.125), hi/lo split
#pragma unroll
    for (int it = 0; it < 4; it++) {
        int f4 = it*256 + tid;
        int r = f4 >> 4, c4 = (f4 & 15) << 2;
        st_hl_sep(Qh + r*PB + c4, Ql + r*PB + c4,
                  *(const float4*)(g_Qlm + bh*4096 + f4*4));
    }
    __syncthreads();

    float acc[8][4];
#pragma unroll
    for (int n = 0; n < 8; n++) { acc[n][0]=0.f; acc[n][1]=0.f; acc[n][2]=0.f; acc[n][3]=0.f; }
    float rsA = 0.f, rsB = 0.f;
    int rA = w*16 + g, rB = rA + 8;

#pragma unroll 1
    for (int t2 = 0; t2 < 2; t2++) {
        int s0 = sp*256 + wg*128 + t2*64;
#pragma unroll
        for (int it = 0; it < 8; it++) {
            int f4 = it*128 + wtid;
            int r = f4 >> 4, c4 = (f4 & 15) << 2;
            st_hl_sep(Kh + r*PB + c4, Kl + r*PB + c4,
                      *(const float4*)(K + ((size_t)bh*SQ + s0 + r)*64 + c4));
            st_hl_sep(Vh + r*PB + c4, Vl + r*PB + c4,
                      *(const float4*)(V + ((size_t)bh*SQ + s0 + r)*64 + c4));
        }
        asm volatile("bar.sync %0, %1;" :: "r"(wg+1), "r"(128) : "memory");

        // logits = Qlm @ Ktile^T  (B row = n = s)
        float c[8][4];
#pragma unroll
        for (int n = 0; n < 8; n++) { c[n][0]=0.f; c[n][1]=0.f; c[n][2]=0.f; c[n][3]=0.f; }
        mma_16x64<true>(Qh, Ql, rA, rB, Kh, Kl, g, t, c);

        // exp (no max shift; |logit| < ~1) + row sums
        float sA = 0.f, sB = 0.f;
#pragma unroll
        for (int n = 0; n < 8; n++) {
            c[n][0] = __expf(c[n][0]); c[n][1] = __expf(c[n][1]);
            c[n][2] = __expf(c[n][2]); c[n][3] = __expf(c[n][3]);
            sA += c[n][0] + c[n][1];
            sB += c[n][2] + c[n][3];
        }
        sA += __shfl_xor_sync(0xffffffffu, sA, 1);
        sA += __shfl_xor_sync(0xffffffffu, sA, 2);
        sB += __shfl_xor_sync(0xffffffffu, sB, 1);
        sB += __shfl_xor_sync(0xffffffffu, sB, 2);
        rsA += sA; rsB += sB;

        asm volatile("bar.sync %0, %1;" :: "r"(wg+1), "r"(128) : "memory");
        // store P hi/lo into K buffers (warp-local rows)
#pragma unroll
        for (int n = 0; n < 8; n++) {
            int col = n*8 + 2*t;
            float h0 = tf32r(c[n][0]), h1 = tf32r(c[n][1]);
            float h2 = tf32r(c[n][2]), h3 = tf32r(c[n][3]);
            float2 ph0 = {h0, h1}, pl0 = {c[n][0]-h0, c[n][1]-h1};
            float2 ph1 = {h2, h3}, pl1 = {c[n][2]-h2, c[n][3]-h3};
            *(float2*)(Kh + rA*PB + col) = ph0;
            *(float2*)(Kl + rA*PB + col) = pl0;
            *(float2*)(Kh + rB*PB + col) = ph1;
            *(float2*)(Kl + rB*PB + col) = pl1;
        }
        __syncwarp();
        // acc += P @ Vtile  (B row = k = s)
        mma_16x64<false>(Kh, Kl, rA, rB, Vh, Vl, g, t, acc);
        asm volatile("bar.sync %0, %1;" :: "r"(wg+1), "r"(128) : "memory");
    }

    int osp = sp*2 + wg;
    size_t base = ((size_t)osp*BHN + bh)*4096;
#pragma unroll
    for (int n = 0; n < 8; n++) {
        int col = n*8 + 2*t;
        float2 oA = {acc[n][0], acc[n][1]};
        float2 oB = {acc[n][2], acc[n][3]};
        *(float2*)(g_pacc + base + rA*64 + col) = oA;
        *(float2*)(g_pacc + base + rB*64 + col) = oB;
    }
    if (t == 0) {
        g_psum[(osp*BHN+bh)*64 + rA] = rsA;
        g_psum[(osp*BHN+bh)*64 + rB] = rsB;
    }
}

__global__ void __launch_bounds__(256, 1) mega_kernel(const float* __restrict__ K,
                                                      const float* __restrict__ V) {
    extern __shared__ __align__(16) float smg[];
    if (blockIdx.x < 64) newton_body(smg, blockIdx.x);
    else { int id = blockIdx.x - 64; kc_body_mma(K, V, smg, id & (NSPLIT-1), id >> 4); }
}

// ---------------- reduce splits -> F, W = Inv@F ----------------
__global__ void __launch_bounds__(256) reduce_winv_kernel() {
    extern __shared__ __align__(16) float smr[];
    float* Fs = smr;
    float* Iv = smr + 64*PB;
    int bh = blockIdx.x, tid = threadIdx.x;

    for (int idx = tid; idx < 4096; idx += 256)
        Iv[(idx>>6)*PB + (idx&63)] = g_Inv[bh*4096 + idx];

    int d = tid & 63, ig = tid >> 6;
    for (int i = ig; i < 64; i += 4) {
        float tot = 0.f;
#pragma unroll
        for (int s = 0; s < NS2; s++) tot += g_psum[(s*BHN+bh)*64 + i];
        float v = 0.f;
#pragma unroll
        for (int s = 0; s < NS2; s++)
            v += g_pacc[((size_t)s*BHN+bh)*4096 + i*64 + d];
        Fs[i*PB + d] = v / tot;
    }
    __syncthreads();
    int cq = tid & 15, rq = tid >> 4;
    u64t acc[4][2] = {};
    mm64_core(Iv, Fs, rq, cq, acc);
#pragma unroll
    for (int rr = 0; rr < 4; rr++) {
        *(u64t*)(g_W + (size_t)bh*4096 + (rq+16*rr)*64 + 2*cq)      = acc[rr][0];
        *(u64t*)(g_W + (size_t)bh*4096 + (rq+16*rr)*64 + 2*cq + 32) = acc[rr][1];
    }
}

// ---------------- kd: mma tf32, X = softmax(0.125 Q Klm^T) @ W ----------------
__global__ void __launch_bounds__(256, 1) kd_mma(const float* __restrict__ Q,
                                                 float* __restrict__ X) {
    extern __shared__ __align__(16) float sk[];
    float* Qh = sk;                 // 128 x PB (later P hi)
    float* Ql = Qh + 128*PB;        // 128 x PB (later P lo)
    float* Kh = Ql + 128*PB;        // 64 x PB
    float* Kl = Kh + 64*PB;
    float* Wh = Kl + 64*PB;
    float* Wl = Wh + 64*PB;
    int tid = threadIdx.x, lane = tid & 31, wid = tid >> 5;
    int g = lane >> 2, t = lane & 3;
    int tile = blockIdx.x, bh = blockIdx.y;

    const float* q0 = Q + ((size_t)bh*SQ + tile*128)*64;
#pragma unroll
    for (int it = 0; it < 8; it++) {
        int f4 = it*256 + tid;
        int r = f4 >> 4, c4 = (f4 & 15) << 2;
        float4 v = *(const float4*)(q0 + r*64 + c4);
        v.x *= 0.125f; v.y *= 0.125f; v.z *= 0.125f; v.w *= 0.125f;
        st_hl_sep(Qh + r*PB + c4, Ql + r*PB + c4, v);
    }
    const float* kl0 = g_Klm + (size_t)bh*4096;
    const float* w0  = g_W   + (size_t)bh*4096;
#pragma unroll
    for (int it = 0; it < 4; it++) {
        int f4 = it*256 + tid;
        int r = f4 >> 4, c4 = (f4 & 15) << 2;
        st_hl_sep(Kh + r*PB + c4, Kl + r*PB + c4, *(const float4*)(kl0 + r*64 + c4));
        st_hl_sep(Wh + r*PB + c4, Wl + r*PB + c4, *(const float4*)(w0  + r*64 + c4));
    }
    __syncthreads();

    int rA = wid*16 + g, rB = rA + 8;
    float c[8][4];
#pragma unroll
    for (int n = 0; n < 8; n++) { c[n][0]=0.f; c[n][1]=0.f; c[n][2]=0.f; c[n][3]=0.f; }

    // logits = Qs @ Klm^T  (B row = n)
    mma_16x64<true>(Qh, Ql, rA, rB, Kh, Kl, g, t, c);

    // softmax (no max shift; |logit| < ~1)
    float sA = 0.f, sB = 0.f;
#pragma unroll
    for (int n = 0; n < 8; n++) {
        c[n][0] = __expf(c[n][0]); c[n][1] = __expf(c[n][1]);
        c[n][2] = __expf(c[n][2]); c[n][3] = __expf(c[n][3]);
        sA += c[n][0] + c[n][1];
        sB += c[n][2] + c[n][3];
    }
    sA += __shfl_xor_sync(0xffffffffu, sA, 1);
    sA += __shfl_xor_sync(0xffffffffu, sA, 2);
    sB += __shfl_xor_sync(0xffffffffu, sB, 1);
    sB += __shfl_xor_sync(0xffffffffu, sB, 2);
    float rinvA = 1.0f / sA, rinvB = 1.0f / sB;

    // P into Q buffers (warp-local rows; Q consumed)
#pragma unroll
    for (int n = 0; n < 8; n++) {
        int col = n*8 + 2*t;
        float h0 = tf32r(c[n][0]), h1 = tf32r(c[n][1]);
        float h2 = tf32r(c[n][2]), h3 = tf32r(c[n][3]);
        float2 ph0 = {h0, h1}, pl0 = {c[n][0]-h0, c[n][1]-h1};
        float2 ph1 = {h2, h3}, pl1 = {c[n][2]-h2, c[n][3]-h3};
        *(float2*)(Qh + rA*PB + col) = ph0;
        *(float2*)(Ql + rA*PB + col) = pl0;
        *(float2*)(Qh + rB*PB + col) = ph1;
        *(float2*)(Ql + rB*PB + col) = pl1;
    }
    __syncwarp();

    // X~ = P @ W  (B row = k)
#pragma unroll
    for (int n = 0; n < 8; n++) { c[n][0]=0.f; c[n][1]=0.f; c[n][2]=0.f; c[n][3]=0.f; }
    mma_16x64<false>(Qh, Ql, rA, rB, Wh, Wl, g, t, c);

    float* x0 = X + ((size_t)bh*SQ + tile*128)*64;
#pragma unroll
    for (int n = 0; n < 8; n++) {
        int col = n*8 + 2*t;
        float2 o0 = {c[n][0]*rinvA, c[n][1]*rinvA};
        float2 o1 = {c[n][2]*rinvB, c[n][3]*rinvB};
        *(float2*)(x0 + rA*64 + col) = o0;
        *(float2*)(x0 + rB*64 + col) = o1;
    }
}

// ---------------- launcher ----------------
extern "C" void kernel_launch(void* const* d_in, const int* in_sizes, int n_in,
                              void* d_out, int out_size) {
    (void)in_sizes; (void)n_in; (void)out_size;
    const float* Q = (const float*)d_in[0];
    const float* K = (const float*)d_in[1];
    const float* V = (const float*)d_in[2];
    float* X = (float*)d_out;

    const int SMEM_MEGA = 10*64*PB*4;                // 174080 (kc); newton uses 87040
    const int SMEM_RW   = 2*64*PB*4;                 // 34816
    const int SMEM_KD   = (2*128 + 4*64)*PB*4;       // 139264
    cudaFuncSetAttribute(mega_kernel,        cudaFuncAttributeMaxDynamicSharedMemorySize, SMEM_MEGA);
    cudaFuncSetAttribute(reduce_winv_kernel, cudaFuncAttributeMaxDynamicSharedMemorySize, SMEM_RW);
    cudaFuncSetAttribute(kd_mma,             cudaFuncAttributeMaxDynamicSharedMemorySize, SMEM_KD);

    pool_kernel<<<BHN*64, 256>>>(Q, K);
    mega_kernel<<<64 + NSPLIT*BHN, 256, SMEM_MEGA>>>(K, V);
    reduce_winv_kernel<<<BHN, 256, SMEM_RW>>>();
    kd_mma<<<dim3(32, BHN), 256, SMEM_KD>>>(Q, X);
}

// round 7
// speedup vs baseline: 1.1861x; 1.0965x over previous
#include <cuda_runtime.h>
#include <cuda_bf16.h>
#include <cstdint>

#define SQ   4096
#define BHN  64
#define PB   68     // fp32 smem pitch (newton / reduce)
#define PW   36     // packed bf16x2 word pitch (32 words data + 4 pad)
#define NS2  32     // softmax splits

typedef unsigned long long u64t;
typedef unsigned int u32;

// ---------------- scratch ----------------
__device__ float g_Qlm [BHN*64*64];   // landmark means of Q, *0.125 folded
__device__ float g_KlmT[BHN*64*64];   // landmark means of K, [d][lm]
__device__ float g_Klm [BHN*64*64];   // landmark means of K, [lm][d]
__device__ float g_Inv [BHN*64*64];   // Newton inverse
__device__ float g_WT  [BHN*64*64];   // (inv@F)^T : [d][m]
__device__ float g_pacc[(size_t)NS2*BHN*64*64];
__device__ float g_psum[NS2*BHN*64];

// ---------------- scalar helpers ----------------
__device__ __forceinline__ u64t pk2(float lo, float hi) {
    u64t r; asm("mov.b64 %0, {%1, %2};" : "=l"(r) : "f"(lo), "f"(hi)); return r;
}
__device__ __forceinline__ u64t ffma2(u64t a, u64t b, u64t c) {
    u64t d; asm("fma.rn.f32x2 %0, %1, %2, %3;" : "=l"(d) : "l"(a), "l"(b), "l"(c)); return d;
}
__device__ __forceinline__ u32 bfpack(float x, float y) {
    __nv_bfloat162 h = __floats2bfloat162_rn(x, y);
    return *reinterpret_cast<u32*>(&h);
}
__device__ __forceinline__ void bfsplit(float x, float y, u32& hw, u32& lw) {
    __nv_bfloat162 h = __floats2bfloat162_rn(x, y);
    float hx = __bfloat162float(h.x), hy = __bfloat162float(h.y);
    hw = *reinterpret_cast<u32*>(&h);
    lw = bfpack(x - hx, y - hy);
}
__device__ __forceinline__ void mmab(float c[4], u32 a0, u32 a1, u32 a2, u32 a3,
                                     u32 b0, u32 b1) {
    asm volatile("mma.sync.aligned.m16n8k16.row.col.f32.bf16.bf16.f32 "
        "{%0,%1,%2,%3}, {%4,%5,%6,%7}, {%8,%9}, {%0,%1,%2,%3};"
        : "+f"(c[0]), "+f"(c[1]), "+f"(c[2]), "+f"(c[3])
        : "r"(a0), "r"(a1), "r"(a2), "r"(a3), "r"(b0), "r"(b1));
}

// warp gemm: C[32x64] += A[32x64] @ B[64x64]^T-frag (split-bf16 3-term)
// A packed [row][kpair] (rows base..base+31), B packed [n][kpair]
__device__ __forceinline__ void wgemm32(const u32* __restrict__ Ah, const u32* __restrict__ Al,
                                        int base,
                                        const u32* __restrict__ Bh, const u32* __restrict__ Bl,
                                        int g, int t, float c[2][8][4]) {
#pragma unroll
    for (int kt = 0; kt < 4; kt++) {
        int w0 = kt*8 + t, w1 = w0 + 4;
        u32 ah[2][4], al[2][4];
#pragma unroll
        for (int s = 0; s < 2; s++) {
            int r0 = base + s*16 + g;
            ah[s][0] = Ah[r0*PW + w0];     ah[s][1] = Ah[(r0+8)*PW + w0];
            ah[s][2] = Ah[r0*PW + w1];     ah[s][3] = Ah[(r0+8)*PW + w1];
            al[s][0] = Al[r0*PW + w0];     al[s][1] = Al[(r0+8)*PW + w0];
            al[s][2] = Al[r0*PW + w1];     al[s][3] = Al[(r0+8)*PW + w1];
        }
#pragma unroll
        for (int nt = 0; nt < 8; nt++) {
            int n0 = nt*8 + g;
            u32 bh0 = Bh[n0*PW + w0], bh1 = Bh[n0*PW + w1];
            u32 bl0 = Bl[n0*PW + w0], bl1 = Bl[n0*PW + w1];
#pragma unroll
            for (int s = 0; s < 2; s++) {
                mmab(c[s][nt], ah[s][0], ah[s][1], ah[s][2], ah[s][3], bh0, bh1);
                mmab(c[s][nt], al[s][0], al[s][1], al[s][2], al[s][3], bh0, bh1);
                mmab(c[s][nt], ah[s][0], ah[s][1], ah[s][2], ah[s][3], bl0, bl1);
            }
        }
    }
}

// write P (in c) into packed A-layout, rows base..base+31 (warp-local)
__device__ __forceinline__ void write_P(u32* Ph, u32* Pl, int base, int g, int t,
                                        const float c[2][8][4]) {
#pragma unroll
    for (int s = 0; s < 2; s++) {
        int r0 = base + 16*s + g;
#pragma unroll
        for (int nt = 0; nt < 8; nt++) {
            u32 hw, lw;
            bfsplit(c[s][nt][0], c[s][nt][1], hw, lw);
            Ph[r0*PW + 4*nt + t] = hw;  Pl[r0*PW + 4*nt + t] = lw;
            bfsplit(c[s][nt][2], c[s][nt][3], hw, lw);
            Ph[(r0+8)*PW + 4*nt + t] = hw;  Pl[(r0+8)*PW + 4*nt + t] = lw;
        }
    }
}

// stage row-major fp32 [rows][64] -> packed along k: word[r][q] = (v[2q], v[2q+1])
__device__ __forceinline__ void stage_k(u32* Dh, u32* Dl, const float* __restrict__ src,
                                        int rows, int tid, int nthr, float scale) {
    for (int f = tid; f < rows*16; f += nthr) {
        int r = f >> 4, q = f & 15;
        float4 v = *(const float4*)(src + r*64 + 4*q);
        v.x *= scale; v.y *= scale; v.z *= scale; v.w *= scale;
        u32 h0, l0, h1, l1;
        bfsplit(v.x, v.y, h0, l0);
        bfsplit(v.z, v.w, h1, l1);
        *(u64t*)(Dh + r*PW + 2*q) = (u64t)h0 | ((u64t)h1 << 32);
        *(u64t*)(Dl + r*PW + 2*q) = (u64t)l0 | ((u64t)l1 << 32);
    }
}

// stage V [64 s][64 d] -> packed along s: word[d][sp] = (V[2sp][d], V[2sp+1][d])
__device__ __forceinline__ void stage_v(u32* Dh, u32* Dl, const float* __restrict__ src,
                                        int tid, int nthr) {
    for (int f = tid; f < 512; f += nthr) {
        int c = f & 63, grp = f >> 6;
        int s0 = grp*8;
        float v[8];
#pragma unroll
        for (int j = 0; j < 8; j++) v[j] = src[(s0+j)*64 + c];
        u32 h[4], l[4];
#pragma unroll
        for (int i = 0; i < 4; i++) bfsplit(v[2*i], v[2*i+1], h[i], l[i]);
        *(uint4*)(Dh + c*PW + 4*grp) = make_uint4(h[0], h[1], h[2], h[3]);
        *(uint4*)(Dl + c*PW + 4*grp) = make_uint4(l[0], l[1], l[2], l[3]);
    }
}

// ---------------- plain FFMA2 64x64 matmul (newton / reduce) ----------------
__device__ __forceinline__ void mm64_core(const float* __restrict__ A,
                                          const float* __restrict__ B,
                                          int rq, int cq, u64t acc[4][2]) {
#pragma unroll
    for (int k = 0; k < 64; k++) {
        u64t b0 = *(const u64t*)(B + k*PB + 2*cq);
        u64t b1 = *(const u64t*)(B + k*PB + 2*cq + 32);
#pragma unroll
        for (int r = 0; r < 4; r++) {
            float a = A[(rq + 16*r)*PB + k];
            u64t a2 = pk2(a, a);
            acc[r][0] = ffma2(a2, b0, acc[r][0]);
            acc[r][1] = ffma2(a2, b1, acc[r][1]);
        }
    }
}
__device__ __noinline__ void mm64_smem(const float* __restrict__ A,
                                       const float* __restrict__ B,
                                       float* __restrict__ C, int tid) {
    int cq = tid & 15, rq = tid >> 4;
    u64t acc[4][2] = {};
    mm64_core(A, B, rq, cq, acc);
#pragma unroll
    for (int r = 0; r < 4; r++) {
        *(u64t*)(C + (rq+16*r)*PB + 2*cq)      = acc[r][0];
        *(u64t*)(C + (rq+16*r)*PB + 2*cq + 32) = acc[r][1];
    }
}

// ---------------- pooling ----------------
__global__ void __launch_bounds__(256) pool_kernel(const float* __restrict__ Q,
                                                   const float* __restrict__ K) {
    int bh = blockIdx.x >> 6, lm = blockIdx.x & 63;
    int d = threadIdx.x & 63, rg = threadIdx.x >> 6;
    const float* qb = Q + ((size_t)bh*SQ + lm*64)*64 + d;
    const float* kb = K + ((size_t)bh*SQ + lm*64)*64 + d;
    float sq = 0.f, sk = 0.f;
    for (int r = rg; r < 64; r += 4) { sq += qb[(size_t)r*64]; sk += kb[(size_t)r*64]; }
    __shared__ float shq[256], shk[256];
    shq[threadIdx.x] = sq; shk[threadIdx.x] = sk;
    __syncthreads();
    if (rg == 0) {
        float q = (shq[d] + shq[64+d] + shq[128+d] + shq[192+d]) * (1.0f/512.0f); // mean*0.125
        float k = (shk[d] + shk[64+d] + shk[128+d] + shk[192+d]) * (1.0f/64.0f);
        g_Qlm [bh*4096 + lm*64 + d] = q;
        g_Klm [bh*4096 + lm*64 + d] = k;
        g_KlmT[bh*4096 + d*64 + lm] = k;
    }
}

// ---------------- Newton-Schulz body (FFMA2; hidden in mega) ----------------
__device__ void newton_body(float* sm, int bh) {
    float* A  = sm;
    float* Vb = sm + 1*64*PB;
    float* P  = sm + 2*64*PB;
    float* T  = sm + 3*64*PB;
    float* U  = sm + 4*64*PB;
    __shared__ float nsred[256], nsrow[64], nscol[64], nscale[1];
    int tid = threadIdx.x;

    for (int idx = tid; idx < 4096; idx += 256) {
        int i = idx >> 6, k = idx & 63;
        T[i*PB + k] = g_Qlm[bh*4096 + idx];
        U[i*PB + k] = g_KlmT[bh*4096 + idx];
    }
    __syncthreads();
    mm64_smem(T, U, A, tid);
    __syncthreads();
    {
        int q = tid & 3, r = tid >> 2;
        float* Lr = A + r*PB + q*16;
        float mt = Lr[0];
#pragma unroll
        for (int c = 1; c < 16; c++) mt = fmaxf(mt, Lr[c]);
        nsred[tid] = mt; __syncthreads();
        float m = fmaxf(fmaxf(nsred[r*4], nsred[r*4+1]), fmaxf(nsred[r*4+2], nsred[r*4+3]));
        float ps = 0.f;
#pragma unroll
        for (int c = 0; c < 16; c++) { float e = __expf(Lr[c] - m); Lr[c] = e; ps += e; }
        __syncthreads();
        nsred[tid] = ps; __syncthreads();
        float inv = 1.0f / (nsred[r*4] + nsred[r*4+1] + nsred[r*4+2] + nsred[r*4+3]);
#pragma unroll
        for (int c = 0; c < 16; c++) Lr[c] *= inv;
    }
    __syncthreads();
    if (tid < 64)       { float s = 0.f; for (int j = 0; j < 64; j++) s += A[tid*PB + j]; nsrow[tid] = s; }
    else if (tid < 128) { int c = tid - 64; float s = 0.f; for (int i = 0; i < 64; i++) s += A[i*PB + c]; nscol[c] = s; }
    __syncthreads();
    if (tid == 0) {
        float mr = nsrow[0], mc = nscol[0];
        for (int i = 1; i < 64; i++) { mr = fmaxf(mr, nsrow[i]); mc = fmaxf(mc, nscol[i]); }
        nscale[0] = 1.0f / (mr * mc);
    }
    __syncthreads();
    float sc = nscale[0];
    for (int idx = tid; idx < 4096; idx += 256) {
        int i = idx >> 6, j = idx & 63;
        Vb[j*PB + i] = A[i*PB + j] * sc;
    }
    __syncthreads();
#pragma unroll 1
    for (int it = 0; it < 6; it++) {
        mm64_smem(A, Vb, P, tid); __syncthreads();
        for (int idx = tid; idx < 4096; idx += 256) {
            int i = idx >> 6, j = idx & 63;
            T[i*PB + j] = (i == j ? 7.0f : 0.0f) - P[i*PB + j];
        }
        __syncthreads();
        mm64_smem(P, T, U, tid); __syncthreads();
        for (int idx = tid; idx < 4096; idx += 256) {
            int i = idx >> 6, j = idx & 63;
            T[i*PB + j] = (i == j ? 15.0f : 0.0f) - U[i*PB + j];
        }
        __syncthreads();
        mm64_smem(P, T, U, tid); __syncthreads();
        for (int idx = tid; idx < 4096; idx += 256) {
            int i = idx >> 6, j = idx & 63;
            T[i*PB + j] = (i == j ? 3.25f : 0.0f) - 0.25f * U[i*PB + j];
        }
        __syncthreads();
        mm64_smem(Vb, T, U, tid); __syncthreads();
        float* tmp = Vb; Vb = U; U = tmp;
    }
    for (int idx = tid; idx < 4096; idx += 256) {
        int i = idx >> 6, j = idx & 63;
        g_Inv[bh*4096 + idx] = Vb[i*PB + j];
    }
}

// ---------------- kc body: split-bf16 mma, 4 sub-splits x 2 warps ----------------
__device__ void kc_body(const float* __restrict__ K, const float* __restrict__ V,
                        u32* sm, int blk, int bh) {
    u32* Qlh = sm;
    u32* Qll = sm + 64*PW;
    int tid = threadIdx.x;
    int ss = tid >> 6, stid = tid & 63;
    int w = stid >> 5, lane = tid & 31;
    int g = lane >> 2, t = lane & 3;
    u32* Kh = sm + 2*64*PW + ss*4*64*PW;   // later P hi
    u32* Kl = Kh + 64*PW;                  // later P lo
    u32* Vh = Kl + 64*PW;
    u32* Vl = Vh + 64*PW;

    stage_k(Qlh, Qll, g_Qlm + bh*4096, 64, tid, 256, 1.0f);   // already *0.125
    __syncthreads();

    int base = w*32;
    int barid = ss + 1;
    float acc[2][8][4];
#pragma unroll
    for (int s2 = 0; s2 < 2; s2++)
#pragma unroll
        for (int n = 0; n < 8; n++) { acc[s2][n][0]=0.f; acc[s2][n][1]=0.f; acc[s2][n][2]=0.f; acc[s2][n][3]=0.f; }
    float rs[4] = {0.f, 0.f, 0.f, 0.f};

#pragma unroll 1
    for (int it2 = 0; it2 < 2; it2++) {
        int s0 = blk*512 + ss*128 + it2*64;
        stage_k(Kh, Kl, K + ((size_t)bh*SQ + s0)*64, 64, stid, 64, 1.0f);
        stage_v(Vh, Vl, V + ((size_t)bh*SQ + s0)*64, stid, 64);
        asm volatile("bar.sync %0, %1;" :: "r"(barid), "r"(64) : "memory");

        float c[2][8][4];
#pragma unroll
        for (int s2 = 0; s2 < 2; s2++)
#pragma unroll
            for (int n = 0; n < 8; n++) { c[s2][n][0]=0.f; c[s2][n][1]=0.f; c[s2][n][2]=0.f; c[s2][n][3]=0.f; }
        wgemm32(Qlh, Qll, base, Kh, Kl, g, t, c);            // logits[lm][s]

        // exp (no max shift; |logit| < ~1), accumulate row sums
#pragma unroll
        for (int s2 = 0; s2 < 2; s2++)
#pragma unroll
            for (int n = 0; n < 8; n++) {
                c[s2][n][0] = __expf(c[s2][n][0]); c[s2][n][1] = __expf(c[s2][n][1]);
                c[s2][n][2] = __expf(c[s2][n][2]); c[s2][n][3] = __expf(c[s2][n][3]);
                rs[2*s2+0] += c[s2][n][0] + c[s2][n][1];
                rs[2*s2+1] += c[s2][n][2] + c[s2][n][3];
            }

        asm volatile("bar.sync %0, %1;" :: "r"(barid), "r"(64) : "memory");  // K reads done
        write_P(Kh, Kl, base, g, t, c);                      // P overwrites K
        __syncwarp();                                        // A-side of MMA2 is warp-local
        wgemm32(Kh, Kl, base, Vh, Vl, g, t, acc);            // acc += P @ V
        asm volatile("bar.sync %0, %1;" :: "r"(barid), "r"(64) : "memory");  // before restage
    }

    // epilogue: shfl-reduce sums, store partials
#pragma unroll
    for (int i = 0; i < 4; i++) {
        rs[i] += __shfl_xor_sync(0xffffffffu, rs[i], 1);
        rs[i] += __shfl_xor_sync(0xffffffffu, rs[i], 2);
    }
    int osp = blk*4 + ss;
    size_t pb = ((size_t)osp*BHN + bh)*4096;
#pragma unroll
    for (int s2 = 0; s2 < 2; s2++) {
        int r0 = base + 16*s2 + g;
#pragma unroll
        for (int nt = 0; nt < 8; nt++) {
            int col = 8*nt + 2*t;
            float2 oA = {acc[s2][nt][0], acc[s2][nt][1]};
            float2 oB = {acc[s2][nt][2], acc[s2][nt][3]};
            *(float2*)(g_pacc + pb + r0*64 + col)     = oA;
            *(float2*)(g_pacc + pb + (r0+8)*64 + col) = oB;
        }
    }
    if (t == 0) {
        float* ps = g_psum + (osp*BHN+bh)*64;
        ps[base + g]      = rs[0];
        ps[base + g + 8]  = rs[1];
        ps[base + g + 16] = rs[2];
        ps[base + g + 24] = rs[3];
    }
}

__global__ void __launch_bounds__(256, 1) mega_kernel(const float* __restrict__ K,
                                                      const float* __restrict__ V) {
    extern __shared__ __align__(16) u32 smg[];
    if (blockIdx.x < 64) newton_body((float*)smg, blockIdx.x);
    else { int id = blockIdx.x - 64; kc_body(K, V, smg, id & 7, id >> 3); }
}

// ---------------- reduce splits -> F, W = Inv@F, store W^T ----------------
__global__ void __launch_bounds__(256) reduce_winv_kernel() {
    extern __shared__ __align__(16) float smr[];
    float* Fs = smr;
    float* Iv = smr + 64*PB;
    int bh = blockIdx.x, tid = threadIdx.x;

    for (int idx = tid; idx < 4096; idx += 256)
        Iv[(idx>>6)*PB + (idx&63)] = g_Inv[bh*4096 + idx];

    int d = tid & 63, ig = tid >> 6;
    for (int i = ig; i < 64; i += 4) {
        float tot = 0.f;
#pragma unroll
        for (int s = 0; s < NS2; s++) tot += g_psum[(s*BHN+bh)*64 + i];
        float v = 0.f;
#pragma unroll
        for (int s = 0; s < NS2; s++)
            v += g_pacc[((size_t)s*BHN+bh)*4096 + i*64 + d];
        Fs[i*PB + d] = v / tot;
    }
    __syncthreads();
    int cq = tid & 15, rq = tid >> 4;
    u64t acc[4][2] = {};
    mm64_core(Iv, Fs, rq, cq, acc);
    float* wt = g_WT + (size_t)bh*4096;
#pragma unroll
    for (int rr = 0; rr < 4; rr++) {
        int row = rq + 16*rr;
        float v0, v1, v2, v3;
        asm("mov.b64 {%0, %1}, %2;" : "=f"(v0), "=f"(v1) : "l"(acc[rr][0]));
        asm("mov.b64 {%0, %1}, %2;" : "=f"(v2), "=f"(v3) : "l"(acc[rr][1]));
        wt[(2*cq)*64    + row] = v0;
        wt[(2*cq+1)*64  + row] = v1;
        wt[(2*cq+32)*64 + row] = v2;
        wt[(2*cq+33)*64 + row] = v3;
    }
}

// ---------------- kd: split-bf16 mma, M=32/warp, 128-thr blocks ----------------
__global__ void __launch_bounds__(128, 3) kd_bf(const float* __restrict__ Q,
                                                float* __restrict__ X) {
    extern __shared__ __align__(16) u32 smk[];
    u32* Qh = smk;                 // 128*PW (later P hi)
    u32* Ql = Qh + 128*PW;         // 128*PW (later P lo)
    u32* Kh = Ql + 128*PW;         // 64*PW
    u32* Kl = Kh + 64*PW;
    u32* Wh = Kl + 64*PW;
    u32* Wl = Wh + 64*PW;
    int tid = threadIdx.x, lane = tid & 31, wid = tid >> 5;
    int g = lane >> 2, t = lane & 3;
    int tile = blockIdx.x, bh = blockIdx.y;

    stage_k(Qh, Ql, Q + ((size_t)bh*SQ + tile*128)*64, 128, tid, 128, 0.125f);
    stage_k(Kh, Kl, g_Klm + (size_t)bh*4096, 64, tid, 128, 1.0f);
    stage_k(Wh, Wl, g_WT  + (size_t)bh*4096, 64, tid, 128, 1.0f);  // B[n=d][kpair=m]
    __syncthreads();

    int base = wid*32;
    float c[2][8][4];
#pragma unroll
    for (int s2 = 0; s2 < 2; s2++)
#pragma unroll
        for (int n = 0; n < 8; n++) { c[s2][n][0]=0.f; c[s2][n][1]=0.f; c[s2][n][2]=0.f; c[s2][n][3]=0.f; }

    wgemm32(Qh, Ql, base, Kh, Kl, g, t, c);   // logits [tok][lm]

    // softmax (no max shift)
    float rs[4] = {0.f, 0.f, 0.f, 0.f};
#pragma unroll
    for (int s2 = 0; s2 < 2; s2++)
#pragma unroll
        for (int n = 0; n < 8; n++) {
            c[s2][n][0] = __expf(c[s2][n][0]); c[s2][n][1] = __expf(c[s2][n][1]);
            c[s2][n][2] = __expf(c[s2][n][2]); c[s2][n][3] = __expf(c[s2][n][3]);
            rs[2*s2+0] += c[s2][n][0] + c[s2][n][1];
            rs[2*s2+1] += c[s2][n][2] + c[s2][n][3];
        }
#pragma unroll
    for (int i = 0; i < 4; i++) {
        rs[i] += __shfl_xor_sync(0xffffffffu, rs[i], 1);
        rs[i] += __shfl_xor_sync(0xffffffffu, rs[i], 2);
        rs[i] = 1.0f / rs[i];
    }

    write_P(Qh, Ql, base, g, t, c);   // P overwrites Q (warp-local rows)
    __syncwarp();

#pragma unroll
    for (int s2 = 0; s2 < 2; s2++)
#pragma unroll
        for (int n = 0; n < 8; n++) { c[s2][n][0]=0.f; c[s2][n][1]=0.f; c[s2][n][2]=0.f; c[s2][n][3]=0.f; }
    wgemm32(Qh, Ql, base, Wh, Wl, g, t, c);   // X~ = P @ W

    float* x0 = X + ((size_t)bh*SQ + tile*128)*64;
#pragma unroll
    for (int s2 = 0; s2 < 2; s2++) {
        int r0 = base + 16*s2 + g;
#pragma unroll
        for (int nt = 0; nt < 8; nt++) {
            int col = 8*nt + 2*t;
            float2 o0 = {c[s2][nt][0]*rs[2*s2], c[s2][nt][1]*rs[2*s2]};
            float2 o1 = {c[s2][nt][2]*rs[2*s2+1], c[s2][nt][3]*rs[2*s2+1]};
            *(float2*)(x0 + r0*64 + col)     = o0;
            *(float2*)(x0 + (r0+8)*64 + col) = o1;
        }
    }
}

// ---------------- launcher ----------------
extern "C" void kernel_launch(void* const* d_in, const int* in_sizes, int n_in,
                              void* d_out, int out_size) {
    (void)in_sizes; (void)n_in; (void)out_size;
    const float* Q = (const float*)d_in[0];
    const float* K = (const float*)d_in[1];
    const float* V = (const float*)d_in[2];
    float* X = (float*)d_out;

    const int SMEM_MEGA = 18*64*PW*4;   // 165888 (kc); newton uses 87040
    const int SMEM_RW   = 2*64*PB*4;    // 34816
    const int SMEM_KD   = 512*PW*4;     // 73728 -> up to 3 CTAs/SM
    cudaFuncSetAttribute(mega_kernel,        cudaFuncAttributeMaxDynamicSharedMemorySize, SMEM_MEGA);
    cudaFuncSetAttribute(reduce_winv_kernel, cudaFuncAttributeMaxDynamicSharedMemorySize, SMEM_RW);
    cudaFuncSetAttribute(kd_bf,              cudaFuncAttributeMaxDynamicSharedMemorySize, SMEM_KD);

    pool_kernel<<<BHN*64, 256>>>(Q, K);
    mega_kernel<<<64 + 8*BHN, 256, SMEM_MEGA>>>(K, V);
    reduce_winv_kernel<<<BHN, 256, SMEM_RW>>>();
    kd_bf<<<dim3(32, BHN), 128, SMEM_KD>>>(Q, X);
}

// round 8
// speedup vs baseline: 1.5592x; 1.3145x over previous
#include <cuda_runtime.h>
#include <cuda_bf16.h>
#include <cstdint>

#define SQ   4096
#define BHN  64
#define PB   68     // fp32 smem pitch (newton / reduce)
#define PW   36     // packed bf16x2 word pitch
#define NS2  16     // softmax splits

typedef unsigned long long u64t;
typedef unsigned int u32;

// ---------------- scratch ----------------
__device__ float g_Qlm [BHN*64*64];
__device__ float g_KlmT[BHN*64*64];
__device__ float g_Klm [BHN*64*64];
__device__ float g_Inv [BHN*64*64];
__device__ float g_WT  [BHN*64*64];   // (inv@F)^T : [d][m]
__device__ float g_pacc[(size_t)NS2*BHN*64*64];
__device__ float g_psum[NS2*BHN*64];

// ---------------- scalar helpers ----------------
__device__ __forceinline__ u64t pk2(float lo, float hi) {
    u64t r; asm("mov.b64 %0, {%1, %2};" : "=l"(r) : "f"(lo), "f"(hi)); return r;
}
__device__ __forceinline__ u64t ffma2(u64t a, u64t b, u64t c) {
    u64t d; asm("fma.rn.f32x2 %0, %1, %2, %3;" : "=l"(d) : "l"(a), "l"(b), "l"(c)); return d;
}
__device__ __forceinline__ u32 bfpack(float x, float y) {
    __nv_bfloat162 h = __floats2bfloat162_rn(x, y);
    return *reinterpret_cast<u32*>(&h);
}
__device__ __forceinline__ void bfsplit(float x, float y, u32& hw, u32& lw) {
    __nv_bfloat162 h = __floats2bfloat162_rn(x, y);
    float hx = __bfloat162float(h.x), hy = __bfloat162float(h.y);
    hw = *reinterpret_cast<u32*>(&h);
    lw = bfpack(x - hx, y - hy);
}
__device__ __forceinline__ void mmab(float c[4], u32 a0, u32 a1, u32 a2, u32 a3,
                                     u32 b0, u32 b1) {
    asm volatile("mma.sync.aligned.m16n8k16.row.col.f32.bf16.bf16.f32 "
        "{%0,%1,%2,%3}, {%4,%5,%6,%7}, {%8,%9}, {%0,%1,%2,%3};"
        : "+f"(c[0]), "+f"(c[1]), "+f"(c[2]), "+f"(c[3])
        : "r"(a0), "r"(a1), "r"(a2), "r"(a3), "r"(b0), "r"(b1));
}

// warp gemm: C[16x64] += A[16x64] @ B (split-bf16 3-term), packed word layout
__device__ __forceinline__ void wgemm16(const u32* __restrict__ Ah, const u32* __restrict__ Al,
                                        int base,
                                        const u32* __restrict__ Bh, const u32* __restrict__ Bl,
                                        int g, int t, float c[8][4]) {
#pragma unroll
    for (int kt = 0; kt < 4; kt++) {
        int w0 = kt*8 + t, w1 = w0 + 4;
        int r0 = base + g;
        u32 ah0 = Ah[r0*PW + w0], ah1 = Ah[(r0+8)*PW + w0];
        u32 ah2 = Ah[r0*PW + w1], ah3 = Ah[(r0+8)*PW + w1];
        u32 al0 = Al[r0*PW + w0], al1 = Al[(r0+8)*PW + w0];
        u32 al2 = Al[r0*PW + w1], al3 = Al[(r0+8)*PW + w1];
#pragma unroll
        for (int nt = 0; nt < 8; nt++) {
            int n0 = nt*8 + g;
            u32 bh0 = Bh[n0*PW + w0], bh1 = Bh[n0*PW + w1];
            u32 bl0 = Bl[n0*PW + w0], bl1 = Bl[n0*PW + w1];
            mmab(c[nt], ah0, ah1, ah2, ah3, bh0, bh1);
            mmab(c[nt], al0, al1, al2, al3, bh0, bh1);
            mmab(c[nt], ah0, ah1, ah2, ah3, bl0, bl1);
        }
    }
}

// write P (16 rows, warp-local) into packed A layout
__device__ __forceinline__ void write_P16(u32* Ph, u32* Pl, int base, int g, int t,
                                          const float c[8][4]) {
    int r0 = base + g;
#pragma unroll
    for (int nt = 0; nt < 8; nt++) {
        u32 hw, lw;
        bfsplit(c[nt][0], c[nt][1], hw, lw);
        Ph[r0*PW + 4*nt + t] = hw;  Pl[r0*PW + 4*nt + t] = lw;
        bfsplit(c[nt][2], c[nt][3], hw, lw);
        Ph[(r0+8)*PW + 4*nt + t] = hw;  Pl[(r0+8)*PW + 4*nt + t] = lw;
    }
}

// stage row-major fp32 [rows][64] -> packed along k
__device__ __forceinline__ void stage_k(u32* Dh, u32* Dl, const float* __restrict__ src,
                                        int rows, int tid, int nthr, float scale) {
    for (int f = tid; f < rows*16; f += nthr) {
        int r = f >> 4, q = f & 15;
        float4 v = *(const float4*)(src + r*64 + 4*q);
        v.x *= scale; v.y *= scale; v.z *= scale; v.w *= scale;
        u32 h0, l0, h1, l1;
        bfsplit(v.x, v.y, h0, l0);
        bfsplit(v.z, v.w, h1, l1);
        *(u64t*)(Dh + r*PW + 2*q) = (u64t)h0 | ((u64t)h1 << 32);
        *(u64t*)(Dl + r*PW + 2*q) = (u64t)l0 | ((u64t)l1 << 32);
    }
}

// stage V [64 s][64 d] -> packed along s
__device__ __forceinline__ void stage_v(u32* Dh, u32* Dl, const float* __restrict__ src,
                                        int tid, int nthr) {
    for (int f = tid; f < 512; f += nthr) {
        int c = f & 63, grp = f >> 6;
        int s0 = grp*8;
        float v[8];
#pragma unroll
        for (int j = 0; j < 8; j++) v[j] = src[(s0+j)*64 + c];
        u32 h[4], l[4];
#pragma unroll
        for (int i = 0; i < 4; i++) bfsplit(v[2*i], v[2*i+1], h[i], l[i]);
        *(uint4*)(Dh + c*PW + 4*grp) = make_uint4(h[0], h[1], h[2], h[3]);
        *(uint4*)(Dl + c*PW + 4*grp) = make_uint4(l[0], l[1], l[2], l[3]);
    }
}

// ---------------- plain FFMA2 64x64 matmul (newton / reduce) ----------------
__device__ __forceinline__ void mm64_core(const float* __restrict__ A,
                                          const float* __restrict__ B,
                                          int rq, int cq, u64t acc[4][2]) {
#pragma unroll
    for (int k = 0; k < 64; k++) {
        u64t b0 = *(const u64t*)(B + k*PB + 2*cq);
        u64t b1 = *(const u64t*)(B + k*PB + 2*cq + 32);
#pragma unroll
        for (int r = 0; r < 4; r++) {
            float a = A[(rq + 16*r)*PB + k];
            u64t a2 = pk2(a, a);
            acc[r][0] = ffma2(a2, b0, acc[r][0]);
            acc[r][1] = ffma2(a2, b1, acc[r][1]);
        }
    }
}
__device__ __noinline__ void mm64_smem(const float* __restrict__ A,
                                       const float* __restrict__ B,
                                       float* __restrict__ C, int tid) {
    int cq = tid & 15, rq = tid >> 4;
    u64t acc[4][2] = {};
    mm64_core(A, B, rq, cq, acc);
#pragma unroll
    for (int r = 0; r < 4; r++) {
        *(u64t*)(C + (rq+16*r)*PB + 2*cq)      = acc[r][0];
        *(u64t*)(C + (rq+16*r)*PB + 2*cq + 32) = acc[r][1];
    }
}

// ---------------- pooling ----------------
__global__ void __launch_bounds__(256) pool_kernel(const float* __restrict__ Q,
                                                   const float* __restrict__ K) {
    int bh = blockIdx.x >> 6, lm = blockIdx.x & 63;
    int d = threadIdx.x & 63, rg = threadIdx.x >> 6;
    const float* qb = Q + ((size_t)bh*SQ + lm*64)*64 + d;
    const float* kb = K + ((size_t)bh*SQ + lm*64)*64 + d;
    float sq = 0.f, sk = 0.f;
    for (int r = rg; r < 64; r += 4) { sq += qb[(size_t)r*64]; sk += kb[(size_t)r*64]; }
    __shared__ float shq[256], shk[256];
    shq[threadIdx.x] = sq; shk[threadIdx.x] = sk;
    __syncthreads();
    if (rg == 0) {
        float q = (shq[d] + shq[64+d] + shq[128+d] + shq[192+d]) * (1.0f/512.0f);
        float k = (shk[d] + shk[64+d] + shk[128+d] + shk[192+d]) * (1.0f/64.0f);
        g_Qlm [bh*4096 + lm*64 + d] = q;
        g_Klm [bh*4096 + lm*64 + d] = k;
        g_KlmT[bh*4096 + d*64 + lm] = k;
    }
}

// ---------------- Newton-Schulz body (FFMA2; hidden in mega) ----------------
__device__ void newton_body(float* sm, int bh) {
    float* A  = sm;
    float* Vb = sm + 1*64*PB;
    float* P  = sm + 2*64*PB;
    float* T  = sm + 3*64*PB;
    float* U  = sm + 4*64*PB;
    __shared__ float nsred[256], nsrow[64], nscol[64], nscale[1];
    int tid = threadIdx.x;

    for (int idx = tid; idx < 4096; idx += 256) {
        int i = idx >> 6, k = idx & 63;
        T[i*PB + k] = g_Qlm[bh*4096 + idx];
        U[i*PB + k] = g_KlmT[bh*4096 + idx];
    }
    __syncthreads();
    mm64_smem(T, U, A, tid);
    __syncthreads();
    {
        int q = tid & 3, r = tid >> 2;
        float* Lr = A + r*PB + q*16;
        float mt = Lr[0];
#pragma unroll
        for (int c = 1; c < 16; c++) mt = fmaxf(mt, Lr[c]);
        nsred[tid] = mt; __syncthreads();
        float m = fmaxf(fmaxf(nsred[r*4], nsred[r*4+1]), fmaxf(nsred[r*4+2], nsred[r*4+3]));
        float ps = 0.f;
#pragma unroll
        for (int c = 0; c < 16; c++) { float e = __expf(Lr[c] - m); Lr[c] = e; ps += e; }
        __syncthreads();
        nsred[tid] = ps; __syncthreads();
        float inv = 1.0f / (nsred[r*4] + nsred[r*4+1] + nsred[r*4+2] + nsred[r*4+3]);
#pragma unroll
        for (int c = 0; c < 16; c++) Lr[c] *= inv;
    }
    __syncthreads();
    if (tid < 64)       { float s = 0.f; for (int j = 0; j < 64; j++) s += A[tid*PB + j]; nsrow[tid] = s; }
    else if (tid < 128) { int c = tid - 64; float s = 0.f; for (int i = 0; i < 64; i++) s += A[i*PB + c]; nscol[c] = s; }
    __syncthreads();
    if (tid == 0) {
        float mr = nsrow[0], mc = nscol[0];
        for (int i = 1; i < 64; i++) { mr = fmaxf(mr, nsrow[i]); mc = fmaxf(mc, nscol[i]); }
        nscale[0] = 1.0f / (mr * mc);
    }
    __syncthreads();
    float sc = nscale[0];
    for (int idx = tid; idx < 4096; idx += 256) {
        int i = idx >> 6, j = idx & 63;
        Vb[j*PB + i] = A[i*PB + j] * sc;
    }
    __syncthreads();
#pragma unroll 1
    for (int it = 0; it < 6; it++) {
        mm64_smem(A, Vb, P, tid); __syncthreads();
        for (int idx = tid; idx < 4096; idx += 256) {
            int i = idx >> 6, j = idx & 63;
            T[i*PB + j] = (i == j ? 7.0f : 0.0f) - P[i*PB + j];
        }
        __syncthreads();
        mm64_smem(P, T, U, tid); __syncthreads();
        for (int idx = tid; idx < 4096; idx += 256) {
            int i = idx >> 6, j = idx & 63;
            T[i*PB + j] = (i == j ? 15.0f : 0.0f) - U[i*PB + j];
        }
        __syncthreads();
        mm64_smem(P, T, U, tid); __syncthreads();
        for (int idx = tid; idx < 4096; idx += 256) {
            int i = idx >> 6, j = idx & 63;
            T[i*PB + j] = (i == j ? 3.25f : 0.0f) - 0.25f * U[i*PB + j];
        }
        __syncthreads();
        mm64_smem(Vb, T, U, tid); __syncthreads();
        float* tmp = Vb; Vb = U; U = tmp;
    }
    for (int idx = tid; idx < 4096; idx += 256) {
        int i = idx >> 6, j = idx & 63;
        g_Inv[bh*4096 + idx] = Vb[i*PB + j];
    }
}

// ---------------- kc body: 2 sub-splits x 4 warps, M=16/warp ----------------
__device__ void kc_body(const float* __restrict__ K, const float* __restrict__ V,
                        u32* sm, int blk, int bh) {
    u32* Qlh = sm;
    u32* Qll = sm + 64*PW;
    int tid = threadIdx.x;
    int ss = tid >> 7, stid = tid & 127;
    int w = stid >> 5, lane = tid & 31;
    int g = lane >> 2, t = lane & 3;
    u32* Kh = sm + 2*64*PW + ss*4*64*PW;   // later P hi
    u32* Kl = Kh + 64*PW;                  // later P lo
    u32* Vh = Kl + 64*PW;
    u32* Vl = Vh + 64*PW;

    stage_k(Qlh, Qll, g_Qlm + bh*4096, 64, tid, 256, 1.0f);   // already *0.125
    __syncthreads();

    int base = w*16;            // lm rows for this warp
    int barid = ss + 1;
    float acc[8][4];
#pragma unroll
    for (int n = 0; n < 8; n++) { acc[n][0]=0.f; acc[n][1]=0.f; acc[n][2]=0.f; acc[n][3]=0.f; }
    float rs0 = 0.f, rs1 = 0.f;

#pragma unroll 1
    for (int it = 0; it < 4; it++) {
        int s0 = blk*512 + ss*256 + it*64;
        stage_k(Kh, Kl, K + ((size_t)bh*SQ + s0)*64, 64, stid, 128, 1.0f);
        stage_v(Vh, Vl, V + ((size_t)bh*SQ + s0)*64, stid, 128);
        asm volatile("bar.sync %0, %1;" :: "r"(barid), "r"(128) : "memory");

        float c[8][4];
#pragma unroll
        for (int n = 0; n < 8; n++) { c[n][0]=0.f; c[n][1]=0.f; c[n][2]=0.f; c[n][3]=0.f; }
        wgemm16(Qlh, Qll, base, Kh, Kl, g, t, c);            // logits[lm][s]

#pragma unroll
        for (int n = 0; n < 8; n++) {
            c[n][0] = __expf(c[n][0]); c[n][1] = __expf(c[n][1]);
            c[n][2] = __expf(c[n][2]); c[n][3] = __expf(c[n][3]);
            rs0 += c[n][0] + c[n][1];
            rs1 += c[n][2] + c[n][3];
        }

        asm volatile("bar.sync %0, %1;" :: "r"(barid), "r"(128) : "memory");  // K reads done
        write_P16(Kh, Kl, base, g, t, c);                    // P overwrites K
        __syncwarp();                                        // A of MMA2 warp-local
        wgemm16(Kh, Kl, base, Vh, Vl, g, t, acc);            // acc += P @ V
        asm volatile("bar.sync %0, %1;" :: "r"(barid), "r"(128) : "memory");  // before restage
    }

    rs0 += __shfl_xor_sync(0xffffffffu, rs0, 1);
    rs0 += __shfl_xor_sync(0xffffffffu, rs0, 2);
    rs1 += __shfl_xor_sync(0xffffffffu, rs1, 1);
    rs1 += __shfl_xor_sync(0xffffffffu, rs1, 2);

    int osp = blk*2 + ss;
    size_t pb = ((size_t)osp*BHN + bh)*4096;
    int r0 = base + g;
#pragma unroll
    for (int nt = 0; nt < 8; nt++) {
        int col = 8*nt + 2*t;
        float2 oA = {acc[nt][0], acc[nt][1]};
        float2 oB = {acc[nt][2], acc[nt][3]};
        *(float2*)(g_pacc + pb + r0*64 + col)     = oA;
        *(float2*)(g_pacc + pb + (r0+8)*64 + col) = oB;
    }
    if (t == 0) {
        float* ps = g_psum + (osp*BHN+bh)*64;
        ps[r0]     = rs0;
        ps[r0 + 8] = rs1;
    }
}

__global__ void __launch_bounds__(256, 2) mega_kernel(const float* __restrict__ K,
                                                      const float* __restrict__ V) {
    extern __shared__ __align__(16) u32 smg[];
    if (blockIdx.x < 64) newton_body((float*)smg, blockIdx.x);
    else { int id = blockIdx.x - 64; kc_body(K, V, smg, id & 7, id >> 3); }
}

// ---------------- reduce splits -> F, W = Inv@F, store W^T ----------------
__global__ void __launch_bounds__(256) reduce_winv_kernel() {
    extern __shared__ __align__(16) float smr[];
    float* Fs = smr;
    float* Iv = smr + 64*PB;
    int bh = blockIdx.x, tid = threadIdx.x;

    for (int idx = tid; idx < 4096; idx += 256)
        Iv[(idx>>6)*PB + (idx&63)] = g_Inv[bh*4096 + idx];

    int d = tid & 63, ig = tid >> 6;
    for (int i = ig; i < 64; i += 4) {
        float tot = 0.f;
#pragma unroll
        for (int s = 0; s < NS2; s++) tot += g_psum[(s*BHN+bh)*64 + i];
        float v = 0.f;
#pragma unroll
        for (int s = 0; s < NS2; s++)
            v += g_pacc[((size_t)s*BHN+bh)*4096 + i*64 + d];
        Fs[i*PB + d] = v / tot;
    }
    __syncthreads();
    int cq = tid & 15, rq = tid >> 4;
    u64t acc[4][2] = {};
    mm64_core(Iv, Fs, rq, cq, acc);
    float* wt = g_WT + (size_t)bh*4096;
#pragma unroll
    for (int rr = 0; rr < 4; rr++) {
        int row = rq + 16*rr;
        float v0, v1, v2, v3;
        asm("mov.b64 {%0, %1}, %2;" : "=f"(v0), "=f"(v1) : "l"(acc[rr][0]));
        asm("mov.b64 {%0, %1}, %2;" : "=f"(v2), "=f"(v3) : "l"(acc[rr][1]));
        wt[(2*cq)*64    + row] = v0;
        wt[(2*cq+1)*64  + row] = v1;
        wt[(2*cq+32)*64 + row] = v2;
        wt[(2*cq+33)*64 + row] = v3;
    }
}

// ---------------- kd: 8 warps, M=16/warp ----------------
__global__ void __launch_bounds__(256, 3) kd_bf(const float* __restrict__ Q,
                                                float* __restrict__ X) {
    extern __shared__ __align__(16) u32 smk[];
    u32* Qh = smk;                 // 128*PW (later P hi)
    u32* Ql = Qh + 128*PW;         // 128*PW (later P lo)
    u32* Kh = Ql + 128*PW;         // 64*PW
    u32* Kl = Kh + 64*PW;
    u32* Wh = Kl + 64*PW;
    u32* Wl = Wh + 64*PW;
    int tid = threadIdx.x, lane = tid & 31, wid = tid >> 5;
    int g = lane >> 2, t = lane & 3;
    int tile = blockIdx.x, bh = blockIdx.y;

    stage_k(Qh, Ql, Q + ((size_t)bh*SQ + tile*128)*64, 128, tid, 256, 0.125f);
    stage_k(Kh, Kl, g_Klm + (size_t)bh*4096, 64, tid, 256, 1.0f);
    stage_k(Wh, Wl, g_WT  + (size_t)bh*4096, 64, tid, 256, 1.0f);
    __syncthreads();

    int base = wid*16;
    float c[8][4];
#pragma unroll
    for (int n = 0; n < 8; n++) { c[n][0]=0.f; c[n][1]=0.f; c[n][2]=0.f; c[n][3]=0.f; }

    wgemm16(Qh, Ql, base, Kh, Kl, g, t, c);   // logits [tok][lm]

    // softmax (no max shift; |logit| < ~1)
    float rs0 = 0.f, rs1 = 0.f;
#pragma unroll
    for (int n = 0; n < 8; n++) {
        c[n][0] = __expf(c[n][0]); c[n][1] = __expf(c[n][1]);
        c[n][2] = __expf(c[n][2]); c[n][3] = __expf(c[n][3]);
        rs0 += c[n][0] + c[n][1];
        rs1 += c[n][2] + c[n][3];
    }
    rs0 += __shfl_xor_sync(0xffffffffu, rs0, 1);
    rs0 += __shfl_xor_sync(0xffffffffu, rs0, 2);
    rs1 += __shfl_xor_sync(0xffffffffu, rs1, 1);
    rs1 += __shfl_xor_sync(0xffffffffu, rs1, 2);
    float rinv0 = 1.0f / rs0, rinv1 = 1.0f / rs1;

    write_P16(Qh, Ql, base, g, t, c);   // P overwrites Q (warp-local rows)
    __syncwarp();

#pragma unroll
    for (int n = 0; n < 8; n++) { c[n][0]=0.f; c[n][1]=0.f; c[n][2]=0.f; c[n][3]=0.f; }
    wgemm16(Qh, Ql, base, Wh, Wl, g, t, c);   // X~ = P @ W

    float* x0 = X + ((size_t)bh*SQ + tile*128)*64;
    int r0 = base + g;
#pragma unroll
    for (int nt = 0; nt < 8; nt++) {
        int col = 8*nt + 2*t;
        float2 o0 = {c[nt][0]*rinv0, c[nt][1]*rinv0};
        float2 o1 = {c[nt][2]*rinv1, c[nt][3]*rinv1};
        *(float2*)(x0 + r0*64 + col)     = o0;
        *(float2*)(x0 + (r0+8)*64 + col) = o1;
    }
}

// ---------------- launcher ----------------
extern "C" void kernel_launch(void* const* d_in, const int* in_sizes, int n_in,
                              void* d_out, int out_size) {
    (void)in_sizes; (void)n_in; (void)out_size;
    const float* Q = (const float*)d_in[0];
    const float* K = (const float*)d_in[1];
    const float* V = (const float*)d_in[2];
    float* X = (float*)d_out;

    const int SMEM_MEGA = 10*64*PW*4;   // 92160 (kc); newton uses 87040 -> 2 CTAs/SM
    const int SMEM_RW   = 2*64*PB*4;    // 34816
    const int SMEM_KD   = 512*PW*4;     // 73728 -> 3 CTAs/SM
    cudaFuncSetAttribute(mega_kernel,        cudaFuncAttributeMaxDynamicSharedMemorySize, SMEM_MEGA);
    cudaFuncSetAttribute(reduce_winv_kernel, cudaFuncAttributeMaxDynamicSharedMemorySize, SMEM_RW);
    cudaFuncSetAttribute(kd_bf,              cudaFuncAttributeMaxDynamicSharedMemorySize, SMEM_KD);

    pool_kernel<<<BHN*64, 256>>>(Q, K);
    mega_kernel<<<64 + 8*BHN, 256, SMEM_MEGA>>>(K, V);
    reduce_winv_kernel<<<BHN, 256, SMEM_RW>>>();
    kd_bf<<<dim3(32, BHN), 256, SMEM_KD>>>(Q, X);
}

// round 10
// speedup vs baseline: 1.7024x; 1.0918x over previous
#include <cuda_runtime.h>
#include <cuda_bf16.h>
#include <cstdint>

#define SQ   4096
#define BHN  64
#define PB   68     // fp32 smem pitch (floats)
#define PW   36     // packed bf16x2 word pitch
#define NS2  16     // softmax splits

typedef unsigned long long u64t;
typedef unsigned int u32;

// ---------------- scratch ----------------
__device__ float g_Qlm [BHN*64*64];
__device__ float g_KlmT[BHN*64*64];
__device__ float g_Klm [BHN*64*64];
__device__ float g_Inv [BHN*64*64];
__device__ float g_WT  [BHN*64*64];   // (inv@F)^T : [d][m]
__device__ float g_pacc[(size_t)NS2*BHN*64*64];
__device__ float g_psum[NS2*BHN*64];

// ---------------- scalar helpers ----------------
__device__ __forceinline__ u64t pk2(float lo, float hi) {
    u64t r; asm("mov.b64 %0, {%1, %2};" : "=l"(r) : "f"(lo), "f"(hi)); return r;
}
__device__ __forceinline__ u64t ffma2(u64t a, u64t b, u64t c) {
    u64t d; asm("fma.rn.f32x2 %0, %1, %2, %3;" : "=l"(d) : "l"(a), "l"(b), "l"(c)); return d;
}
__device__ __forceinline__ u32 bfpack(float x, float y) {
    __nv_bfloat162 h = __floats2bfloat162_rn(x, y);
    return *reinterpret_cast<u32*>(&h);
}
__device__ __forceinline__ void bfsplit(float x, float y, u32& hw, u32& lw) {
    __nv_bfloat162 h = __floats2bfloat162_rn(x, y);
    float hx = __bfloat162float(h.x), hy = __bfloat162float(h.y);
    hw = *reinterpret_cast<u32*>(&h);
    lw = bfpack(x - hx, y - hy);
}
__device__ __forceinline__ void mmab(float c[4], u32 a0, u32 a1, u32 a2, u32 a3,
                                     u32 b0, u32 b1) {
    asm volatile("mma.sync.aligned.m16n8k16.row.col.f32.bf16.bf16.f32 "
        "{%0,%1,%2,%3}, {%4,%5,%6,%7}, {%8,%9}, {%0,%1,%2,%3};"
        : "+f"(c[0]), "+f"(c[1]), "+f"(c[2]), "+f"(c[3])
        : "r"(a0), "r"(a1), "r"(a2), "r"(a3), "r"(b0), "r"(b1));
}

// warp gemm: C[16x64] += A[16 rows] @ B (split-bf16 3-term), packed word layout
__device__ __forceinline__ void wgemm16(const u32* __restrict__ Ah, const u32* __restrict__ Al,
                                        int base,
                                        const u32* __restrict__ Bh, const u32* __restrict__ Bl,
                                        int g, int t, float c[8][4]) {
#pragma unroll
    for (int kt = 0; kt < 4; kt++) {
        int w0 = kt*8 + t, w1 = w0 + 4;
        int r0 = base + g;
        u32 ah0 = Ah[r0*PW + w0], ah1 = Ah[(r0+8)*PW + w0];
        u32 ah2 = Ah[r0*PW + w1], ah3 = Ah[(r0+8)*PW + w1];
        u32 al0 = Al[r0*PW + w0], al1 = Al[(r0+8)*PW + w0];
        u32 al2 = Al[r0*PW + w1], al3 = Al[(r0+8)*PW + w1];
#pragma unroll
        for (int nt = 0; nt < 8; nt++) {
            int n0 = nt*8 + g;
            u32 bh0 = Bh[n0*PW + w0], bh1 = Bh[n0*PW + w1];
            u32 bl0 = Bl[n0*PW + w0], bl1 = Bl[n0*PW + w1];
            mmab(c[nt], ah0, ah1, ah2, ah3, bh0, bh1);
            mmab(c[nt], al0, al1, al2, al3, bh0, bh1);
            mmab(c[nt], ah0, ah1, ah2, ah3, bl0, bl1);
        }
    }
}

// write P (16 rows, warp-local) into packed A layout
__device__ __forceinline__ void write_P16(u32* Ph, u32* Pl, int base, int g, int t,
                                          const float c[8][4]) {
    int r0 = base + g;
#pragma unroll
    for (int nt = 0; nt < 8; nt++) {
        u32 hw, lw;
        bfsplit(c[nt][0], c[nt][1], hw, lw);
        Ph[r0*PW + 4*nt + t] = hw;  Pl[r0*PW + 4*nt + t] = lw;
        bfsplit(c[nt][2], c[nt][3], hw, lw);
        Ph[(r0+8)*PW + 4*nt + t] = hw;  Pl[(r0+8)*PW + 4*nt + t] = lw;
    }
}

// stage row-major fp32 [rows][64] -> packed along k
__device__ __forceinline__ void stage_k(u32* Dh, u32* Dl, const float* __restrict__ src,
                                        int rows, int tid, int nthr, float scale) {
    for (int f = tid; f < rows*16; f += nthr) {
        int r = f >> 4, q = f & 15;
        float4 v = *(const float4*)(src + r*64 + 4*q);
        v.x *= scale; v.y *= scale; v.z *= scale; v.w *= scale;
        u32 h0, l0, h1, l1;
        bfsplit(v.x, v.y, h0, l0);
        bfsplit(v.z, v.w, h1, l1);
        *(u64t*)(Dh + r*PW + 2*q) = (u64t)h0 | ((u64t)h1 << 32);
        *(u64t*)(Dl + r*PW + 2*q) = (u64t)l0 | ((u64t)l1 << 32);
    }
}

// stage V [64 s][64 d] -> packed along s
__device__ __forceinline__ void stage_v(u32* Dh, u32* Dl, const float* __restrict__ src,
                                        int tid, int nthr) {
    for (int f = tid; f < 512; f += nthr) {
        int c = f & 63, grp = f >> 6;
        int s0 = grp*8;
        float v[8];
#pragma unroll
        for (int j = 0; j < 8; j++) v[j] = src[(s0+j)*64 + c];
        u32 h[4], l[4];
#pragma unroll
        for (int i = 0; i < 4; i++) bfsplit(v[2*i], v[2*i+1], h[i], l[i]);
        *(uint4*)(Dh + c*PW + 4*grp) = make_uint4(h[0], h[1], h[2], h[3]);
        *(uint4*)(Dl + c*PW + 4*grp) = make_uint4(l[0], l[1], l[2], l[3]);
    }
}

// ---------------- plain FFMA2 64x64 matmul (newton / reduce) ----------------
__device__ __forceinline__ void mm64_core(const float* __restrict__ A,
                                          const float* __restrict__ B,
                                          int rq, int cq, u64t acc[4][2]) {
#pragma unroll
    for (int k = 0; k < 64; k++) {
        u64t b0 = *(const u64t*)(B + k*PB + 2*cq);
        u64t b1 = *(const u64t*)(B + k*PB + 2*cq + 32);
#pragma unroll
        for (int r = 0; r < 4; r++) {
            float a = A[(rq + 16*r)*PB + k];
            u64t a2 = pk2(a, a);
            acc[r][0] = ffma2(a2, b0, acc[r][0]);
            acc[r][1] = ffma2(a2, b1, acc[r][1]);
        }
    }
}
__device__ __noinline__ void mm64_smem(const float* __restrict__ A,
                                       const float* __restrict__ B,
                                       float* __restrict__ C, int tid) {
    int cq = tid & 15, rq = tid >> 4;
    u64t acc[4][2] = {};
    mm64_core(A, B, rq, cq, acc);
#pragma unroll
    for (int r = 0; r < 4; r++) {
        *(u64t*)(C + (rq+16*r)*PB + 2*cq)      = acc[r][0];
        *(u64t*)(C + (rq+16*r)*PB + 2*cq + 32) = acc[r][1];
    }
}

// ---------------- pooling ----------------
__global__ void __launch_bounds__(256) pool_kernel(const float* __restrict__ Q,
                                                   const float* __restrict__ K) {
    int bh = blockIdx.x >> 6, lm = blockIdx.x & 63;
    int d = threadIdx.x & 63, rg = threadIdx.x >> 6;
    const float* qb = Q + ((size_t)bh*SQ + lm*64)*64 + d;
    const float* kb = K + ((size_t)bh*SQ + lm*64)*64 + d;
    float sq = 0.f, sk = 0.f;
    for (int r = rg; r < 64; r += 4) { sq += qb[(size_t)r*64]; sk += kb[(size_t)r*64]; }
    __shared__ float shq[256], shk[256];
    shq[threadIdx.x] = sq; shk[threadIdx.x] = sk;
    __syncthreads();
    if (rg == 0) {
        float q = (shq[d] + shq[64+d] + shq[128+d] + shq[192+d]) * (1.0f/512.0f);
        float k = (shk[d] + shk[64+d] + shk[128+d] + shk[192+d]) * (1.0f/64.0f);
        g_Qlm [bh*4096 + lm*64 + d] = q;
        g_Klm [bh*4096 + lm*64 + d] = k;
        g_KlmT[bh*4096 + d*64 + lm] = k;
    }
}

// ---------------- Newton-Schulz body (FFMA2 fp32; exact trajectory) ----------------
__device__ void newton_body(float* sm, int bh) {
    float* A  = sm;
    float* Vb = sm + 1*64*PB;
    float* P  = sm + 2*64*PB;
    float* T  = sm + 3*64*PB;
    float* U  = sm + 4*64*PB;
    __shared__ float nsred[256], nsrow[64], nscol[64], nscale[1];
    int tid = threadIdx.x;

    for (int idx = tid; idx < 4096; idx += 256) {
        int i = idx >> 6, k = idx & 63;
        T[i*PB + k] = g_Qlm[bh*4096 + idx];
        U[i*PB + k] = g_KlmT[bh*4096 + idx];
    }
    __syncthreads();
    mm64_smem(T, U, A, tid);
    __syncthreads();
    {
        int q = tid & 3, r = tid >> 2;
        float* Lr = A + r*PB + q*16;
        float mt = Lr[0];
#pragma unroll
        for (int c = 1; c < 16; c++) mt = fmaxf(mt, Lr[c]);
        nsred[tid] = mt; __syncthreads();
        float m = fmaxf(fmaxf(nsred[r*4], nsred[r*4+1]), fmaxf(nsred[r*4+2], nsred[r*4+3]));
        float ps = 0.f;
#pragma unroll
        for (int c = 0; c < 16; c++) { float e = __expf(Lr[c] - m); Lr[c] = e; ps += e; }
        __syncthreads();
        nsred[tid] = ps; __syncthreads();
        float inv = 1.0f / (nsred[r*4] + nsred[r*4+1] + nsred[r*4+2] + nsred[r*4+3]);
#pragma unroll
        for (int c = 0; c < 16; c++) Lr[c] *= inv;
    }
    __syncthreads();
    if (tid < 64)       { float s = 0.f; for (int j = 0; j < 64; j++) s += A[tid*PB + j]; nsrow[tid] = s; }
    else if (tid < 128) { int c = tid - 64; float s = 0.f; for (int i = 0; i < 64; i++) s += A[i*PB + c]; nscol[c] = s; }
    __syncthreads();
    if (tid == 0) {
        float mr = nsrow[0], mc = nscol[0];
        for (int i = 1; i < 64; i++) { mr = fmaxf(mr, nsrow[i]); mc = fmaxf(mc, nscol[i]); }
        nscale[0] = 1.0f / (mr * mc);
    }
    __syncthreads();
    float sc = nscale[0];
    for (int idx = tid; idx < 4096; idx += 256) {
        int i = idx >> 6, j = idx & 63;
        Vb[j*PB + i] = A[i*PB + j] * sc;
    }
    __syncthreads();
#pragma unroll 1
    for (int it = 0; it < 6; it++) {
        mm64_smem(A, Vb, P, tid); __syncthreads();
        for (int idx = tid; idx < 4096; idx += 256) {
            int i = idx >> 6, j = idx & 63;
            T[i*PB + j] = (i == j ? 7.0f : 0.0f) - P[i*PB + j];
        }
        __syncthreads();
        mm64_smem(P, T, U, tid); __syncthreads();
        for (int idx = tid; idx < 4096; idx += 256) {
            int i = idx >> 6, j = idx & 63;
            T[i*PB + j] = (i == j ? 15.0f : 0.0f) - U[i*PB + j];
        }
        __syncthreads();
        mm64_smem(P, T, U, tid); __syncthreads();
        for (int idx = tid; idx < 4096; idx += 256) {
            int i = idx >> 6, j = idx & 63;
            T[i*PB + j] = (i == j ? 3.25f : 0.0f) - 0.25f * U[i*PB + j];
        }
        __syncthreads();
        mm64_smem(Vb, T, U, tid); __syncthreads();
        float* tmp = Vb; Vb = U; U = tmp;
    }
    for (int idx = tid; idx < 4096; idx += 256) {
        int i = idx >> 6, j = idx & 63;
        g_Inv[bh*4096 + idx] = Vb[i*PB + j];
    }
}

// ---------------- kc body: 2 sub-splits x 4 warps, M=16/warp ----------------
__device__ void kc_body(const float* __restrict__ K, const float* __restrict__ V,
                        u32* sm, int blk, int bh) {
    u32* Qlh = sm;
    u32* Qll = sm + 64*PW;
    int tid = threadIdx.x;
    int ss = tid >> 7, stid = tid & 127;
    int w = stid >> 5, lane = tid & 31;
    int g = lane >> 2, t = lane & 3;
    u32* Kh = sm + 2*64*PW + ss*4*64*PW;
    u32* Kl = Kh + 64*PW;
    u32* Vh = Kl + 64*PW;
    u32* Vl = Vh + 64*PW;

    stage_k(Qlh, Qll, g_Qlm + bh*4096, 64, tid, 256, 1.0f);
    __syncthreads();

    int base = w*16;
    int barid = ss + 1;
    float acc[8][4];
#pragma unroll
    for (int n = 0; n < 8; n++) { acc[n][0]=0.f; acc[n][1]=0.f; acc[n][2]=0.f; acc[n][3]=0.f; }
    float rs0 = 0.f, rs1 = 0.f;

#pragma unroll 1
    for (int it = 0; it < 4; it++) {
        int s0 = blk*512 + ss*256 + it*64;
        stage_k(Kh, Kl, K + ((size_t)bh*SQ + s0)*64, 64, stid, 128, 1.0f);
        stage_v(Vh, Vl, V + ((size_t)bh*SQ + s0)*64, stid, 128);
        asm volatile("bar.sync %0, %1;" :: "r"(barid), "r"(128) : "memory");

        float c[8][4];
#pragma unroll
        for (int n = 0; n < 8; n++) { c[n][0]=0.f; c[n][1]=0.f; c[n][2]=0.f; c[n][3]=0.f; }
        wgemm16(Qlh, Qll, base, Kh, Kl, g, t, c);

#pragma unroll
        for (int n = 0; n < 8; n++) {
            c[n][0] = __expf(c[n][0]); c[n][1] = __expf(c[n][1]);
            c[n][2] = __expf(c[n][2]); c[n][3] = __expf(c[n][3]);
            rs0 += c[n][0] + c[n][1];
            rs1 += c[n][2] + c[n][3];
        }

        asm volatile("bar.sync %0, %1;" :: "r"(barid), "r"(128) : "memory");
        write_P16(Kh, Kl, base, g, t, c);
        __syncwarp();
        wgemm16(Kh, Kl, base, Vh, Vl, g, t, acc);
        asm volatile("bar.sync %0, %1;" :: "r"(barid), "r"(128) : "memory");
    }

    rs0 += __shfl_xor_sync(0xffffffffu, rs0, 1);
    rs0 += __shfl_xor_sync(0xffffffffu, rs0, 2);
    rs1 += __shfl_xor_sync(0xffffffffu, rs1, 1);
    rs1 += __shfl_xor_sync(0xffffffffu, rs1, 2);

    int osp = blk*2 + ss;
    size_t pb = ((size_t)osp*BHN + bh)*4096;
    int r0 = base + g;
#pragma unroll
    for (int nt = 0; nt < 8; nt++) {
        int col = 8*nt + 2*t;
        *(float2*)(g_pacc + pb + r0*64 + col)     = make_float2(acc[nt][0], acc[nt][1]);
        *(float2*)(g_pacc + pb + (r0+8)*64 + col) = make_float2(acc[nt][2], acc[nt][3]);
    }
    if (t == 0) {
        float* ps = g_psum + (osp*BHN+bh)*64;
        ps[r0]     = rs0;
        ps[r0 + 8] = rs1;
    }
}

__global__ void __launch_bounds__(256, 2) mega_kernel(const float* __restrict__ K,
                                                      const float* __restrict__ V) {
    extern __shared__ __align__(16) u32 smg[];
    if (blockIdx.x < 64) newton_body((float*)smg, blockIdx.x);
    else { int id = blockIdx.x - 64; kc_body(K, V, smg, id & 7, id >> 3); }
}

// ---------------- reduce splits -> F, W = Inv@F, store W^T ----------------
__global__ void __launch_bounds__(256) reduce_winv_kernel() {
    extern __shared__ __align__(16) float smr[];
    float* Fs = smr;
    float* Iv = smr + 64*PB;
    int bh = blockIdx.x, tid = threadIdx.x;

    for (int idx = tid; idx < 4096; idx += 256)
        Iv[(idx>>6)*PB + (idx&63)] = g_Inv[bh*4096 + idx];

    int d = tid & 63, ig = tid >> 6;
    for (int i = ig; i < 64; i += 4) {
        float tot = 0.f;
#pragma unroll
        for (int s = 0; s < NS2; s++) tot += g_psum[(s*BHN+bh)*64 + i];
        float v = 0.f;
#pragma unroll
        for (int s = 0; s < NS2; s++)
            v += g_pacc[((size_t)s*BHN+bh)*4096 + i*64 + d];
        Fs[i*PB + d] = v / tot;
    }
    __syncthreads();
    int cq = tid & 15, rq = tid >> 4;
    u64t acc[4][2] = {};
    mm64_core(Iv, Fs, rq, cq, acc);
    float* wt = g_WT + (size_t)bh*4096;
#pragma unroll
    for (int rr = 0; rr < 4; rr++) {
        int row = rq + 16*rr;
        float v0, v1, v2, v3;
        asm("mov.b64 {%0, %1}, %2;" : "=f"(v0), "=f"(v1) : "l"(acc[rr][0]));
        asm("mov.b64 {%0, %1}, %2;" : "=f"(v2), "=f"(v3) : "l"(acc[rr][1]));
        wt[(2*cq)*64    + row] = v0;
        wt[(2*cq+1)*64  + row] = v1;
        wt[(2*cq+32)*64 + row] = v2;
        wt[(2*cq+33)*64 + row] = v3;
    }
}

// ---------------- kd: 8 warps, M=16/warp, 2 tiles per CTA ----------------
__global__ void __launch_bounds__(256, 3) kd_bf(const float* __restrict__ Q,
                                                float* __restrict__ X) {
    extern __shared__ __align__(16) u32 smk[];
    u32* Qh = smk;
    u32* Ql = Qh + 128*PW;
    u32* Kh = Ql + 128*PW;
    u32* Kl = Kh + 64*PW;
    u32* Wh = Kl + 64*PW;
    u32* Wl = Wh + 64*PW;
    int tid = threadIdx.x, lane = tid & 31, wid = tid >> 5;
    int g = lane >> 2, t = lane & 3;
    int bh = blockIdx.y;

    stage_k(Kh, Kl, g_Klm + (size_t)bh*4096, 64, tid, 256, 1.0f);
    stage_k(Wh, Wl, g_WT  + (size_t)bh*4096, 64, tid, 256, 1.0f);

    int base = wid*16;
    int r0 = base + g;

#pragma unroll 1
    for (int t2 = 0; t2 < 2; t2++) {
        int tile = blockIdx.x*2 + t2;
        if (t2) __syncthreads();    // all P reads done before Q restage
        stage_k(Qh, Ql, Q + ((size_t)bh*SQ + tile*128)*64, 128, tid, 256, 0.125f);
        __syncthreads();

        float c[8][4];
#pragma unroll
        for (int n = 0; n < 8; n++) { c[n][0]=0.f; c[n][1]=0.f; c[n][2]=0.f; c[n][3]=0.f; }
        wgemm16(Qh, Ql, base, Kh, Kl, g, t, c);   // logits [tok][lm]

        float rs0 = 0.f, rs1 = 0.f;
#pragma unroll
        for (int n = 0; n < 8; n++) {
            c[n][0] = __expf(c[n][0]); c[n][1] = __expf(c[n][1]);
            c[n][2] = __expf(c[n][2]); c[n][3] = __expf(c[n][3]);
            rs0 += c[n][0] + c[n][1];
            rs1 += c[n][2] + c[n][3];
        }
        rs0 += __shfl_xor_sync(0xffffffffu, rs0, 1);
        rs0 += __shfl_xor_sync(0xffffffffu, rs0, 2);
        rs1 += __shfl_xor_sync(0xffffffffu, rs1, 1);
        rs1 += __shfl_xor_sync(0xffffffffu, rs1, 2);
        float rinv0 = 1.0f / rs0, rinv1 = 1.0f / rs1;

        write_P16(Qh, Ql, base, g, t, c);
        __syncwarp();

#pragma unroll
        for (int n = 0; n < 8; n++) { c[n][0]=0.f; c[n][1]=0.f; c[n][2]=0.f; c[n][3]=0.f; }
        wgemm16(Qh, Ql, base, Wh, Wl, g, t, c);   // X~ = P @ W

        float* x0 = X + ((size_t)bh*SQ + tile*128)*64;
#pragma unroll
        for (int nt = 0; nt < 8; nt++) {
            int col = 8*nt + 2*t;
            *(float2*)(x0 + r0*64 + col)     = make_float2(c[nt][0]*rinv0, c[nt][1]*rinv0);
            *(float2*)(x0 + (r0+8)*64 + col) = make_float2(c[nt][2]*rinv1, c[nt][3]*rinv1);
        }
    }
}

// ---------------- launcher ----------------
extern "C" void kernel_launch(void* const* d_in, const int* in_sizes, int n_in,
                              void* d_out, int out_size) {
    (void)in_sizes; (void)n_in; (void)out_size;
    const float* Q = (const float*)d_in[0];
    const float* K = (const float*)d_in[1];
    const float* V = (const float*)d_in[2];
    float* X = (float*)d_out;

    const int SMEM_MEGA = 10*64*PW*4;   // 92160 (kc); newton (fp32) uses 87040 -> 2 CTAs/SM
    const int SMEM_RW   = 2*64*PB*4;    // 34816
    const int SMEM_KD   = 512*PW*4;     // 73728 -> 3 CTAs/SM
    cudaFuncSetAttribute(mega_kernel,        cudaFuncAttributeMaxDynamicSharedMemorySize, SMEM_MEGA);
    cudaFuncSetAttribute(reduce_winv_kernel, cudaFuncAttributeMaxDynamicSharedMemorySize, SMEM_RW);
    cudaFuncSetAttribute(kd_bf,              cudaFuncAttributeMaxDynamicSharedMemorySize, SMEM_KD);

    pool_kernel<<<BHN*64, 256>>>(Q, K);
    mega_kernel<<<64 + 8*BHN, 256, SMEM_MEGA>>>(K, V);
    reduce_winv_kernel<<<BHN, 256, SMEM_RW>>>();
    kd_bf<<<dim3(16, BHN), 256, SMEM_KD>>>(Q, X);
}

// round 11
// speedup vs baseline: 1.7458x; 1.0255x over previous
#include <cuda_runtime.h>
#include <cuda_bf16.h>
#include <cstdint>

#define SQ   4096
#define BHN  64
#define PB   68     // fp32 smem pitch (floats)
#define PW   36     // packed bf16x2 word pitch
#define NS2  16     // softmax splits

typedef unsigned long long u64t;
typedef unsigned int u32;

// ---------------- scratch ----------------
__device__ float g_Qlm [BHN*64*64];
__device__ float g_KlmT[BHN*64*64];
__device__ float g_Klm [BHN*64*64];
__device__ float g_Inv [BHN*64*64];
__device__ float g_WT  [BHN*64*64];   // (inv@F)^T : [d][m]
__device__ float g_pacc[(size_t)NS2*BHN*64*64];
__device__ float g_psum[NS2*BHN*64];

// ---------------- scalar helpers ----------------
__device__ __forceinline__ u64t pk2(float lo, float hi) {
    u64t r; asm("mov.b64 %0, {%1, %2};" : "=l"(r) : "f"(lo), "f"(hi)); return r;
}
__device__ __forceinline__ u64t ffma2(u64t a, u64t b, u64t c) {
    u64t d; asm("fma.rn.f32x2 %0, %1, %2, %3;" : "=l"(d) : "l"(a), "l"(b), "l"(c)); return d;
}
__device__ __forceinline__ u32 bfpack(float x, float y) {
    __nv_bfloat162 h = __floats2bfloat162_rn(x, y);
    return *reinterpret_cast<u32*>(&h);
}
__device__ __forceinline__ void bfsplit(float x, float y, u32& hw, u32& lw) {
    __nv_bfloat162 h = __floats2bfloat162_rn(x, y);
    float hx = __bfloat162float(h.x), hy = __bfloat162float(h.y);
    hw = *reinterpret_cast<u32*>(&h);
    lw = bfpack(x - hx, y - hy);
}
__device__ __forceinline__ void mmab(float c[4], u32 a0, u32 a1, u32 a2, u32 a3,
                                     u32 b0, u32 b1) {
    asm volatile("mma.sync.aligned.m16n8k16.row.col.f32.bf16.bf16.f32 "
        "{%0,%1,%2,%3}, {%4,%5,%6,%7}, {%8,%9}, {%0,%1,%2,%3};"
        : "+f"(c[0]), "+f"(c[1]), "+f"(c[2]), "+f"(c[3])
        : "r"(a0), "r"(a1), "r"(a2), "r"(a3), "r"(b0), "r"(b1));
}
__device__ __forceinline__ u32 sptr(const void* p) {
    u32 a;
    asm("{ .reg .u64 t; cvta.to.shared.u64 t, %1; cvt.u32.u64 %0, t; }" : "=r"(a) : "l"(p));
    return a;
}
__device__ __forceinline__ void ldsm4(u32* r, u32 addr) {
    asm volatile("ldmatrix.sync.aligned.m8n8.x4.shared.b16 {%0,%1,%2,%3}, [%4];"
        : "=r"(r[0]), "=r"(r[1]), "=r"(r[2]), "=r"(r[3]) : "r"(addr));
}

// warp gemm: C[16x64] += A[16 rows] @ B (split-bf16 3-term, ldmatrix fragments)
// A packed [row][kpair] rows base..base+15; B packed [n][kpair]
__device__ __forceinline__ void wgemm16(const u32* __restrict__ Ah, const u32* __restrict__ Al,
                                        int base,
                                        const u32* __restrict__ Bh, const u32* __restrict__ Bl,
                                        int lane, float c[8][4]) {
    int mi = lane >> 3, lr = lane & 7;
    u32 aH = sptr(Ah + (base + (mi & 1)*8 + lr)*PW + (mi >> 1)*4);
    u32 aL = sptr(Al + (base + (mi & 1)*8 + lr)*PW + (mi >> 1)*4);
    u32 bH = sptr(Bh + ((mi >> 1)*8 + lr)*PW + (mi & 1)*4);
    u32 bL = sptr(Bl + ((mi >> 1)*8 + lr)*PW + (mi & 1)*4);
#pragma unroll
    for (int kt = 0; kt < 4; kt++) {
        u32 ah[4], al[4];
        ldsm4(ah, aH + kt*32);
        ldsm4(al, aL + kt*32);
#pragma unroll
        for (int p = 0; p < 4; p++) {
            u32 bh[4], bl[4];
            ldsm4(bh, bH + p*(16*PW*4) + kt*32);
            ldsm4(bl, bL + p*(16*PW*4) + kt*32);
            mmab(c[2*p],   ah[0],ah[1],ah[2],ah[3], bh[0],bh[1]);
            mmab(c[2*p],   al[0],al[1],al[2],al[3], bh[0],bh[1]);
            mmab(c[2*p],   ah[0],ah[1],ah[2],ah[3], bl[0],bl[1]);
            mmab(c[2*p+1], ah[0],ah[1],ah[2],ah[3], bh[2],bh[3]);
            mmab(c[2*p+1], al[0],al[1],al[2],al[3], bh[2],bh[3]);
            mmab(c[2*p+1], ah[0],ah[1],ah[2],ah[3], bl[2],bl[3]);
        }
    }
}

// write P (16 rows, warp-local) into packed A layout
__device__ __forceinline__ void write_P16(u32* Ph, u32* Pl, int base, int g, int t,
                                          const float c[8][4]) {
    int r0 = base + g;
#pragma unroll
    for (int nt = 0; nt < 8; nt++) {
        u32 hw, lw;
        bfsplit(c[nt][0], c[nt][1], hw, lw);
        Ph[r0*PW + 4*nt + t] = hw;  Pl[r0*PW + 4*nt + t] = lw;
        bfsplit(c[nt][2], c[nt][3], hw, lw);
        Ph[(r0+8)*PW + 4*nt + t] = hw;  Pl[(r0+8)*PW + 4*nt + t] = lw;
    }
}

// stage row-major fp32 [rows][64] -> packed along k
__device__ __forceinline__ void stage_k(u32* Dh, u32* Dl, const float* __restrict__ src,
                                        int rows, int tid, int nthr, float scale) {
    for (int f = tid; f < rows*16; f += nthr) {
        int r = f >> 4, q = f & 15;
        float4 v = *(const float4*)(src + r*64 + 4*q);
        v.x *= scale; v.y *= scale; v.z *= scale; v.w *= scale;
        u32 h0, l0, h1, l1;
        bfsplit(v.x, v.y, h0, l0);
        bfsplit(v.z, v.w, h1, l1);
        *(u64t*)(Dh + r*PW + 2*q) = (u64t)h0 | ((u64t)h1 << 32);
        *(u64t*)(Dl + r*PW + 2*q) = (u64t)l0 | ((u64t)l1 << 32);
    }
}

// stage V [64 s][64 d] -> packed along s
__device__ __forceinline__ void stage_v(u32* Dh, u32* Dl, const float* __restrict__ src,
                                        int tid, int nthr) {
    for (int f = tid; f < 512; f += nthr) {
        int c = f & 63, grp = f >> 6;
        int s0 = grp*8;
        float v[8];
#pragma unroll
        for (int j = 0; j < 8; j++) v[j] = src[(s0+j)*64 + c];
        u32 h[4], l[4];
#pragma unroll
        for (int i = 0; i < 4; i++) bfsplit(v[2*i], v[2*i+1], h[i], l[i]);
        *(uint4*)(Dh + c*PW + 4*grp) = make_uint4(h[0], h[1], h[2], h[3]);
        *(uint4*)(Dl + c*PW + 4*grp) = make_uint4(l[0], l[1], l[2], l[3]);
    }
}

// ---------------- plain FFMA2 64x64 matmul core ----------------
__device__ __forceinline__ void mm64_core(const float* __restrict__ A,
                                          const float* __restrict__ B,
                                          int rq, int cq, u64t acc[4][2]) {
#pragma unroll
    for (int k = 0; k < 64; k++) {
        u64t b0 = *(const u64t*)(B + k*PB + 2*cq);
        u64t b1 = *(const u64t*)(B + k*PB + 2*cq + 32);
#pragma unroll
        for (int r = 0; r < 4; r++) {
            float a = A[(rq + 16*r)*PB + k];
            u64t a2 = pk2(a, a);
            acc[r][0] = ffma2(a2, b0, acc[r][0]);
            acc[r][1] = ffma2(a2, b1, acc[r][1]);
        }
    }
}
__device__ __noinline__ void mm64_smem(const float* __restrict__ A,
                                       const float* __restrict__ B,
                                       float* __restrict__ C, int tid) {
    int cq = tid & 15, rq = tid >> 4;
    u64t acc[4][2] = {};
    mm64_core(A, B, rq, cq, acc);
#pragma unroll
    for (int r = 0; r < 4; r++) {
        *(u64t*)(C + (rq+16*r)*PB + 2*cq)      = acc[r][0];
        *(u64t*)(C + (rq+16*r)*PB + 2*cq + 32) = acc[r][1];
    }
}
// matmul with fused transform epilogue: optional raw store + Ct = aI - bS*C
__device__ __noinline__ void mm64_tr(const float* __restrict__ A,
                                     const float* __restrict__ B,
                                     float* __restrict__ Craw, float* __restrict__ Ct,
                                     float aI, float bS, int tid) {
    int cq = tid & 15, rq = tid >> 4;
    u64t acc[4][2] = {};
    mm64_core(A, B, rq, cq, acc);
    int j0 = 2*cq, j2 = 2*cq + 32;
#pragma unroll
    for (int r = 0; r < 4; r++) {
        int row = rq + 16*r;
        if (Craw) {
            *(u64t*)(Craw + row*PB + j0) = acc[r][0];
            *(u64t*)(Craw + row*PB + j2) = acc[r][1];
        }
        float v0, v1, v2, v3;
        asm("mov.b64 {%0, %1}, %2;" : "=f"(v0), "=f"(v1) : "l"(acc[r][0]));
        asm("mov.b64 {%0, %1}, %2;" : "=f"(v2), "=f"(v3) : "l"(acc[r][1]));
        float t0 = (row == j0   ? aI : 0.f) - bS*v0;
        float t1 = (row == j0+1 ? aI : 0.f) - bS*v1;
        float t2 = (row == j2   ? aI : 0.f) - bS*v2;
        float t3 = (row == j2+1 ? aI : 0.f) - bS*v3;
        *(u64t*)(Ct + row*PB + j0) = pk2(t0, t1);
        *(u64t*)(Ct + row*PB + j2) = pk2(t2, t3);
    }
}

// ---------------- pooling ----------------
__global__ void __launch_bounds__(256) pool_kernel(const float* __restrict__ Q,
                                                   const float* __restrict__ K) {
    int bh = blockIdx.x >> 6, lm = blockIdx.x & 63;
    int d = threadIdx.x & 63, rg = threadIdx.x >> 6;
    const float* qb = Q + ((size_t)bh*SQ + lm*64)*64 + d;
    const float* kb = K + ((size_t)bh*SQ + lm*64)*64 + d;
    float sq = 0.f, sk = 0.f;
    for (int r = rg; r < 64; r += 4) { sq += qb[(size_t)r*64]; sk += kb[(size_t)r*64]; }
    __shared__ float shq[256], shk[256];
    shq[threadIdx.x] = sq; shk[threadIdx.x] = sk;
    __syncthreads();
    if (rg == 0) {
        float q = (shq[d] + shq[64+d] + shq[128+d] + shq[192+d]) * (1.0f/512.0f);
        float k = (shk[d] + shk[64+d] + shk[128+d] + shk[192+d]) * (1.0f/64.0f);
        g_Qlm [bh*4096 + lm*64 + d] = q;
        g_Klm [bh*4096 + lm*64 + d] = k;
        g_KlmT[bh*4096 + d*64 + lm] = k;
    }
}

// ---------------- Newton-Schulz body (FFMA2 fp32; fused transforms) ----------------
__device__ void newton_body(float* sm, int bh) {
    float* A  = sm;
    float* Vb = sm + 1*64*PB;
    float* P  = sm + 2*64*PB;
    float* T  = sm + 3*64*PB;
    float* U  = sm + 4*64*PB;
    __shared__ float nsred[256], nsrow[64], nscol[64], nscale[1];
    int tid = threadIdx.x;

    for (int idx = tid; idx < 4096; idx += 256) {
        int i = idx >> 6, k = idx & 63;
        T[i*PB + k] = g_Qlm[bh*4096 + idx];
        U[i*PB + k] = g_KlmT[bh*4096 + idx];
    }
    __syncthreads();
    mm64_smem(T, U, A, tid);
    __syncthreads();
    {
        int q = tid & 3, r = tid >> 2;
        float* Lr = A + r*PB + q*16;
        float mt = Lr[0];
#pragma unroll
        for (int c = 1; c < 16; c++) mt = fmaxf(mt, Lr[c]);
        nsred[tid] = mt; __syncthreads();
        float m = fmaxf(fmaxf(nsred[r*4], nsred[r*4+1]), fmaxf(nsred[r*4+2], nsred[r*4+3]));
        float ps = 0.f;
#pragma unroll
        for (int c = 0; c < 16; c++) { float e = __expf(Lr[c] - m); Lr[c] = e; ps += e; }
        __syncthreads();
        nsred[tid] = ps; __syncthreads();
        float inv = 1.0f / (nsred[r*4] + nsred[r*4+1] + nsred[r*4+2] + nsred[r*4+3]);
#pragma unroll
        for (int c = 0; c < 16; c++) Lr[c] *= inv;
    }
    __syncthreads();
    if (tid < 64)       { float s = 0.f; for (int j = 0; j < 64; j++) s += A[tid*PB + j]; nsrow[tid] = s; }
    else if (tid < 128) { int c = tid - 64; float s = 0.f; for (int i = 0; i < 64; i++) s += A[i*PB + c]; nscol[c] = s; }
    __syncthreads();
    if (tid == 0) {
        float mr = nsrow[0], mc = nscol[0];
        for (int i = 1; i < 64; i++) { mr = fmaxf(mr, nsrow[i]); mc = fmaxf(mc, nscol[i]); }
        nscale[0] = 1.0f / (mr * mc);
    }
    __syncthreads();
    float sc = nscale[0];
    for (int idx = tid; idx < 4096; idx += 256) {
        int i = idx >> 6, j = idx & 63;
        Vb[j*PB + i] = A[i*PB + j] * sc;
    }
    __syncthreads();
#pragma unroll 1
    for (int it = 0; it < 6; it++) {
        mm64_tr(A,  Vb, P, T, 7.0f,  1.0f,  tid); __syncthreads();   // P raw, T1=7I-P
        mm64_tr(P,  T,  (float*)0, U, 15.0f, 1.0f, tid); __syncthreads(); // T2=15I-PT1
        mm64_tr(P,  U,  (float*)0, T, 3.25f, 0.25f, tid); __syncthreads();// T3=0.25(13I-PT2)
        mm64_smem(Vb, T, U, tid); __syncthreads();                   // Vnew = Vb@T3
        float* tmp = Vb; Vb = U; U = tmp;
    }
    for (int idx = tid; idx < 4096; idx += 256) {
        int i = idx >> 6, j = idx & 63;
        g_Inv[bh*4096 + idx] = Vb[i*PB + j];
    }
}

// ---------------- kc body: 2 sub-splits x 4 warps, M=16/warp ----------------
__device__ void kc_body(const float* __restrict__ K, const float* __restrict__ V,
                        u32* sm, int blk, int bh) {
    u32* Qlh = sm;
    u32* Qll = sm + 64*PW;
    int tid = threadIdx.x;
    int ss = tid >> 7, stid = tid & 127;
    int w = stid >> 5, lane = tid & 31;
    int g = lane >> 2, t = lane & 3;
    u32* Kh = sm + 2*64*PW + ss*4*64*PW;
    u32* Kl = Kh + 64*PW;
    u32* Vh = Kl + 64*PW;
    u32* Vl = Vh + 64*PW;

    stage_k(Qlh, Qll, g_Qlm + bh*4096, 64, tid, 256, 1.0f);
    __syncthreads();

    int base = w*16;
    int barid = ss + 1;
    float acc[8][4];
#pragma unroll
    for (int n = 0; n < 8; n++) { acc[n][0]=0.f; acc[n][1]=0.f; acc[n][2]=0.f; acc[n][3]=0.f; }
    float rs0 = 0.f, rs1 = 0.f;

#pragma unroll 1
    for (int it = 0; it < 4; it++) {
        int s0 = blk*512 + ss*256 + it*64;
        stage_k(Kh, Kl, K + ((size_t)bh*SQ + s0)*64, 64, stid, 128, 1.0f);
        stage_v(Vh, Vl, V + ((size_t)bh*SQ + s0)*64, stid, 128);
        asm volatile("bar.sync %0, %1;" :: "r"(barid), "r"(128) : "memory");

        float c[8][4];
#pragma unroll
        for (int n = 0; n < 8; n++) { c[n][0]=0.f; c[n][1]=0.f; c[n][2]=0.f; c[n][3]=0.f; }
        wgemm16(Qlh, Qll, base, Kh, Kl, lane, c);

#pragma unroll
        for (int n = 0; n < 8; n++) {
            c[n][0] = __expf(c[n][0]); c[n][1] = __expf(c[n][1]);
            c[n][2] = __expf(c[n][2]); c[n][3] = __expf(c[n][3]);
            rs0 += c[n][0] + c[n][1];
            rs1 += c[n][2] + c[n][3];
        }

        asm volatile("bar.sync %0, %1;" :: "r"(barid), "r"(128) : "memory");
        write_P16(Kh, Kl, base, g, t, c);
        __syncwarp();
        wgemm16(Kh, Kl, base, Vh, Vl, lane, acc);
        asm volatile("bar.sync %0, %1;" :: "r"(barid), "r"(128) : "memory");
    }

    rs0 += __shfl_xor_sync(0xffffffffu, rs0, 1);
    rs0 += __shfl_xor_sync(0xffffffffu, rs0, 2);
    rs1 += __shfl_xor_sync(0xffffffffu, rs1, 1);
    rs1 += __shfl_xor_sync(0xffffffffu, rs1, 2);

    int osp = blk*2 + ss;
    size_t pb = ((size_t)osp*BHN + bh)*4096;
    int r0 = base + g;
#pragma unroll
    for (int nt = 0; nt < 8; nt++) {
        int col = 8*nt + 2*t;
        *(float2*)(g_pacc + pb + r0*64 + col)     = make_float2(acc[nt][0], acc[nt][1]);
        *(float2*)(g_pacc + pb + (r0+8)*64 + col) = make_float2(acc[nt][2], acc[nt][3]);
    }
    if (t == 0) {
        float* ps = g_psum + (osp*BHN+bh)*64;
        ps[r0]     = rs0;
        ps[r0 + 8] = rs1;
    }
}

__global__ void __launch_bounds__(256, 2) mega_kernel(const float* __restrict__ K,
                                                      const float* __restrict__ V) {
    extern __shared__ __align__(16) u32 smg[];
    if (blockIdx.x < 64) newton_body((float*)smg, blockIdx.x);
    else { int id = blockIdx.x - 64; kc_body(K, V, smg, id & 7, id >> 3); }
}

// ---------------- reduce splits -> F, W = Inv@F, store W^T ----------------
__global__ void __launch_bounds__(256) reduce_winv_kernel() {
    extern __shared__ __align__(16) float smr[];
    float* Fs = smr;
    float* Iv = smr + 64*PB;
    int bh = blockIdx.x, tid = threadIdx.x;

    for (int idx = tid; idx < 4096; idx += 256)
        Iv[(idx>>6)*PB + (idx&63)] = g_Inv[bh*4096 + idx];

    int d = tid & 63, ig = tid >> 6;
    for (int i = ig; i < 64; i += 4) {
        float tot = 0.f;
#pragma unroll
        for (int s = 0; s < NS2; s++) tot += g_psum[(s*BHN+bh)*64 + i];
        float v = 0.f;
#pragma unroll
        for (int s = 0; s < NS2; s++)
            v += g_pacc[((size_t)s*BHN+bh)*4096 + i*64 + d];
        Fs[i*PB + d] = v / tot;
    }
    __syncthreads();
    int cq = tid & 15, rq = tid >> 4;
    u64t acc[4][2] = {};
    mm64_core(Iv, Fs, rq, cq, acc);
    float* wt = g_WT + (size_t)bh*4096;
#pragma unroll
    for (int rr = 0; rr < 4; rr++) {
        int row = rq + 16*rr;
        float v0, v1, v2, v3;
        asm("mov.b64 {%0, %1}, %2;" : "=f"(v0), "=f"(v1) : "l"(acc[rr][0]));
        asm("mov.b64 {%0, %1}, %2;" : "=f"(v2), "=f"(v3) : "l"(acc[rr][1]));
        wt[(2*cq)*64    + row] = v0;
        wt[(2*cq+1)*64  + row] = v1;
        wt[(2*cq+32)*64 + row] = v2;
        wt[(2*cq+33)*64 + row] = v3;
    }
}

// ---------------- kd: 8 warps, M=16/warp, 2 tiles per CTA ----------------
__global__ void __launch_bounds__(256, 3) kd_bf(const float* __restrict__ Q,
                                                float* __restrict__ X) {
    extern __shared__ __align__(16) u32 smk[];
    u32* Qh = smk;
    u32* Ql = Qh + 128*PW;
    u32* Kh = Ql + 128*PW;
    u32* Kl = Kh + 64*PW;
    u32* Wh = Kl + 64*PW;
    u32* Wl = Wh + 64*PW;
    int tid = threadIdx.x, lane = tid & 31, wid = tid >> 5;
    int g = lane >> 2, t = lane & 3;
    int bh = blockIdx.y;

    stage_k(Kh, Kl, g_Klm + (size_t)bh*4096, 64, tid, 256, 1.0f);
    stage_k(Wh, Wl, g_WT  + (size_t)bh*4096, 64, tid, 256, 1.0f);

    int base = wid*16;
    int r0 = base + g;

#pragma unroll 1
    for (int t2 = 0; t2 < 2; t2++) {
        int tile = blockIdx.x*2 + t2;
        if (t2) __syncthreads();    // all P reads done before Q restage
        stage_k(Qh, Ql, Q + ((size_t)bh*SQ + tile*128)*64, 128, tid, 256, 0.125f);
        __syncthreads();

        float c[8][4];
#pragma unroll
        for (int n = 0; n < 8; n++) { c[n][0]=0.f; c[n][1]=0.f; c[n][2]=0.f; c[n][3]=0.f; }
        wgemm16(Qh, Ql, base, Kh, Kl, lane, c);   // logits [tok][lm]

        float rs0 = 0.f, rs1 = 0.f;
#pragma unroll
        for (int n = 0; n < 8; n++) {
            c[n][0] = __expf(c[n][0]); c[n][1] = __expf(c[n][1]);
            c[n][2] = __expf(c[n][2]); c[n][3] = __expf(c[n][3]);
            rs0 += c[n][0] + c[n][1];
            rs1 += c[n][2] + c[n][3];
        }
        rs0 += __shfl_xor_sync(0xffffffffu, rs0, 1);
        rs0 += __shfl_xor_sync(0xffffffffu, rs0, 2);
        rs1 += __shfl_xor_sync(0xffffffffu, rs1, 1);
        rs1 += __shfl_xor_sync(0xffffffffu, rs1, 2);
        float rinv0 = 1.0f / rs0, rinv1 = 1.0f / rs1;

        write_P16(Qh, Ql, base, g, t, c);
        __syncwarp();

#pragma unroll
        for (int n = 0; n < 8; n++) { c[n][0]=0.f; c[n][1]=0.f; c[n][2]=0.f; c[n][3]=0.f; }
        wgemm16(Qh, Ql, base, Wh, Wl, lane, c);   // X~ = P @ W

        float* x0 = X + ((size_t)bh*SQ + tile*128)*64;
#pragma unroll
        for (int nt = 0; nt < 8; nt++) {
            int col = 8*nt + 2*t;
            *(float2*)(x0 + r0*64 + col)     = make_float2(c[nt][0]*rinv0, c[nt][1]*rinv0);
            *(float2*)(x0 + (r0+8)*64 + col) = make_float2(c[nt][2]*rinv1, c[nt][3]*rinv1);
        }
    }
}

// ---------------- launcher ----------------
extern "C" void kernel_launch(void* const* d_in, const int* in_sizes, int n_in,
                              void* d_out, int out_size) {
    (void)in_sizes; (void)n_in; (void)out_size;
    const float* Q = (const float*)d_in[0];
    const float* K = (const float*)d_in[1];
    const float* V = (const float*)d_in[2];
    float* X = (float*)d_out;

    const int SMEM_MEGA = 10*64*PW*4;   // 92160 (kc); newton (fp32) uses 87040 -> 2 CTAs/SM
    const int SMEM_RW   = 2*64*PB*4;    // 34816
    const int SMEM_KD   = 512*PW*4;     // 73728 -> 3 CTAs/SM
    cudaFuncSetAttribute(mega_kernel,        cudaFuncAttributeMaxDynamicSharedMemorySize, SMEM_MEGA);
    cudaFuncSetAttribute(reduce_winv_kernel, cudaFuncAttributeMaxDynamicSharedMemorySize, SMEM_RW);
    cudaFuncSetAttribute(kd_bf,              cudaFuncAttributeMaxDynamicSharedMemorySize, SMEM_KD);

    pool_kernel<<<BHN*64, 256>>>(Q, K);
    mega_kernel<<<64 + 8*BHN, 256, SMEM_MEGA>>>(K, V);
    reduce_winv_kernel<<<BHN, 256, SMEM_RW>>>();
    kd_bf<<<dim3(16, BHN), 256, SMEM_KD>>>(Q, X);
}

// round 12
// speedup vs baseline: 1.7875x; 1.0239x over previous
#include <cuda_runtime.h>
#include <cuda_bf16.h>
#include <cstdint>

#define SQ   4096
#define BHN  64
#define PB   68     // fp32 smem pitch (floats)
#define PW   36     // packed bf16x2 word pitch
#define NS2  16     // softmax splits

typedef unsigned long long u64t;
typedef unsigned int u32;

// ---------------- scratch ----------------
__device__ float g_Qlm [BHN*64*64];
__device__ float g_KlmT[BHN*64*64];
__device__ float g_Klm [BHN*64*64];
__device__ float g_Inv [BHN*64*64];
__device__ float g_WT  [BHN*64*64];   // (inv@F)^T : [d][m]
__device__ float g_pacc[(size_t)NS2*BHN*64*64];
__device__ float g_psum[NS2*BHN*64];

// ---------------- scalar helpers ----------------
__device__ __forceinline__ u64t pk2(float lo, float hi) {
    u64t r; asm("mov.b64 %0, {%1, %2};" : "=l"(r) : "f"(lo), "f"(hi)); return r;
}
__device__ __forceinline__ u64t ffma2(u64t a, u64t b, u64t c) {
    u64t d; asm("fma.rn.f32x2 %0, %1, %2, %3;" : "=l"(d) : "l"(a), "l"(b), "l"(c)); return d;
}
__device__ __forceinline__ u32 bfpack(float x, float y) {
    __nv_bfloat162 h = __floats2bfloat162_rn(x, y);
    return *reinterpret_cast<u32*>(&h);
}
__device__ __forceinline__ void bfsplit(float x, float y, u32& hw, u32& lw) {
    __nv_bfloat162 h = __floats2bfloat162_rn(x, y);
    float hx = __bfloat162float(h.x), hy = __bfloat162float(h.y);
    hw = *reinterpret_cast<u32*>(&h);
    lw = bfpack(x - hx, y - hy);
}
__device__ __forceinline__ void mmab(float c[4], u32 a0, u32 a1, u32 a2, u32 a3,
                                     u32 b0, u32 b1) {
    asm volatile("mma.sync.aligned.m16n8k16.row.col.f32.bf16.bf16.f32 "
        "{%0,%1,%2,%3}, {%4,%5,%6,%7}, {%8,%9}, {%0,%1,%2,%3};"
        : "+f"(c[0]), "+f"(c[1]), "+f"(c[2]), "+f"(c[3])
        : "r"(a0), "r"(a1), "r"(a2), "r"(a3), "r"(b0), "r"(b1));
}
__device__ __forceinline__ u32 sptr(const void* p) {
    u32 a;
    asm("{ .reg .u64 t; cvta.to.shared.u64 t, %1; cvt.u32.u64 %0, t; }" : "=r"(a) : "l"(p));
    return a;
}
__device__ __forceinline__ void ldsm4(u32* r, u32 addr) {
    asm volatile("ldmatrix.sync.aligned.m8n8.x4.shared.b16 {%0,%1,%2,%3}, [%4];"
        : "=r"(r[0]), "=r"(r[1]), "=r"(r[2]), "=r"(r[3]) : "r"(addr));
}

// warp gemm: C[16x64] += A[16 rows, k=64] @ B[64 n, k=64]  (kd)
__device__ __forceinline__ void wgemm16(const u32* __restrict__ Ah, const u32* __restrict__ Al,
                                        int base,
                                        const u32* __restrict__ Bh, const u32* __restrict__ Bl,
                                        int lane, float c[8][4]) {
    int mi = lane >> 3, lr = lane & 7;
    u32 aH = sptr(Ah + (base + (mi & 1)*8 + lr)*PW + (mi >> 1)*4);
    u32 aL = sptr(Al + (base + (mi & 1)*8 + lr)*PW + (mi >> 1)*4);
    u32 bH = sptr(Bh + ((mi >> 1)*8 + lr)*PW + (mi & 1)*4);
    u32 bL = sptr(Bl + ((mi >> 1)*8 + lr)*PW + (mi & 1)*4);
#pragma unroll
    for (int kt = 0; kt < 4; kt++) {
        u32 ah[4], al[4];
        ldsm4(ah, aH + kt*32);
        ldsm4(al, aL + kt*32);
#pragma unroll
        for (int p = 0; p < 4; p++) {
            u32 bh[4], bl[4];
            ldsm4(bh, bH + p*(16*PW*4) + kt*32);
            ldsm4(bl, bL + p*(16*PW*4) + kt*32);
            mmab(c[2*p],   ah[0],ah[1],ah[2],ah[3], bh[0],bh[1]);
            mmab(c[2*p],   al[0],al[1],al[2],al[3], bh[0],bh[1]);
            mmab(c[2*p],   ah[0],ah[1],ah[2],ah[3], bl[0],bl[1]);
            mmab(c[2*p+1], ah[0],ah[1],ah[2],ah[3], bh[2],bh[3]);
            mmab(c[2*p+1], al[0],al[1],al[2],al[3], bh[2],bh[3]);
            mmab(c[2*p+1], ah[0],ah[1],ah[2],ah[3], bl[2],bl[3]);
        }
    }
}

// warp gemm: C[16x32] += A[16 rows, k=64] @ B[n = nbase..nbase+31, k=64]  (kc)
__device__ __forceinline__ void wg16x32(const u32* __restrict__ Ah, const u32* __restrict__ Al,
                                        int base,
                                        const u32* __restrict__ Bh, const u32* __restrict__ Bl,
                                        int nbase, int lane, float c[4][4]) {
    int mi = lane >> 3, lr = lane & 7;
    u32 aH = sptr(Ah + (base + (mi & 1)*8 + lr)*PW + (mi >> 1)*4);
    u32 aL = sptr(Al + (base + (mi & 1)*8 + lr)*PW + (mi >> 1)*4);
    u32 bH = sptr(Bh + (nbase + (mi >> 1)*8 + lr)*PW + (mi & 1)*4);
    u32 bL = sptr(Bl + (nbase + (mi >> 1)*8 + lr)*PW + (mi & 1)*4);
#pragma unroll
    for (int kt = 0; kt < 4; kt++) {
        u32 ah[4], al[4];
        ldsm4(ah, aH + kt*32);
        ldsm4(al, aL + kt*32);
#pragma unroll
        for (int p = 0; p < 2; p++) {
            u32 bh[4], bl[4];
            ldsm4(bh, bH + p*(16*PW*4) + kt*32);
            ldsm4(bl, bL + p*(16*PW*4) + kt*32);
            mmab(c[2*p],   ah[0],ah[1],ah[2],ah[3], bh[0],bh[1]);
            mmab(c[2*p],   al[0],al[1],al[2],al[3], bh[0],bh[1]);
            mmab(c[2*p],   ah[0],ah[1],ah[2],ah[3], bl[0],bl[1]);
            mmab(c[2*p+1], ah[0],ah[1],ah[2],ah[3], bh[2],bh[3]);
            mmab(c[2*p+1], al[0],al[1],al[2],al[3], bh[2],bh[3]);
            mmab(c[2*p+1], ah[0],ah[1],ah[2],ah[3], bl[2],bl[3]);
        }
    }
}

// write P (16 rows, full width) into packed A layout (kd)
__device__ __forceinline__ void write_P16(u32* Ph, u32* Pl, int base, int g, int t,
                                          const float c[8][4]) {
    int r0 = base + g;
#pragma unroll
    for (int nt = 0; nt < 8; nt++) {
        u32 hw, lw;
        bfsplit(c[nt][0], c[nt][1], hw, lw);
        Ph[r0*PW + 4*nt + t] = hw;  Pl[r0*PW + 4*nt + t] = lw;
        bfsplit(c[nt][2], c[nt][3], hw, lw);
        Ph[(r0+8)*PW + 4*nt + t] = hw;  Pl[(r0+8)*PW + 4*nt + t] = lw;
    }
}

// write P (16 rows, 32-col half at word offset co) into packed layout (kc)
__device__ __forceinline__ void write_P32(u32* Ph, u32* Pl, int base, int co, int g, int t,
                                          const float c[4][4]) {
    int r0 = base + g;
#pragma unroll
    for (int nt = 0; nt < 4; nt++) {
        u32 hw, lw;
        bfsplit(c[nt][0], c[nt][1], hw, lw);
        Ph[r0*PW + co + 4*nt + t] = hw;  Pl[r0*PW + co + 4*nt + t] = lw;
        bfsplit(c[nt][2], c[nt][3], hw, lw);
        Ph[(r0+8)*PW + co + 4*nt + t] = hw;  Pl[(r0+8)*PW + co + 4*nt + t] = lw;
    }
}

// stage row-major fp32 [rows][64] -> packed along k
__device__ __forceinline__ void stage_k(u32* Dh, u32* Dl, const float* __restrict__ src,
                                        int rows, int tid, int nthr, float scale) {
    for (int f = tid; f < rows*16; f += nthr) {
        int r = f >> 4, q = f & 15;
        float4 v = *(const float4*)(src + r*64 + 4*q);
        v.x *= scale; v.y *= scale; v.z *= scale; v.w *= scale;
        u32 h0, l0, h1, l1;
        bfsplit(v.x, v.y, h0, l0);
        bfsplit(v.z, v.w, h1, l1);
        *(u64t*)(Dh + r*PW + 2*q) = (u64t)h0 | ((u64t)h1 << 32);
        *(u64t*)(Dl + r*PW + 2*q) = (u64t)l0 | ((u64t)l1 << 32);
    }
}

// stage V [64 s][64 d] -> packed along s
__device__ __forceinline__ void stage_v(u32* Dh, u32* Dl, const float* __restrict__ src,
                                        int tid, int nthr) {
    for (int f = tid; f < 512; f += nthr) {
        int c = f & 63, grp = f >> 6;
        int s0 = grp*8;
        float v[8];
#pragma unroll
        for (int j = 0; j < 8; j++) v[j] = src[(s0+j)*64 + c];
        u32 h[4], l[4];
#pragma unroll
        for (int i = 0; i < 4; i++) bfsplit(v[2*i], v[2*i+1], h[i], l[i]);
        *(uint4*)(Dh + c*PW + 4*grp) = make_uint4(h[0], h[1], h[2], h[3]);
        *(uint4*)(Dl + c*PW + 4*grp) = make_uint4(l[0], l[1], l[2], l[3]);
    }
}

// ---------------- plain FFMA2 64x64 matmul core ----------------
__device__ __forceinline__ void mm64_core(const float* __restrict__ A,
                                          const float* __restrict__ B,
                                          int rq, int cq, u64t acc[4][2]) {
#pragma unroll
    for (int k = 0; k < 64; k++) {
        u64t b0 = *(const u64t*)(B + k*PB + 2*cq);
        u64t b1 = *(const u64t*)(B + k*PB + 2*cq + 32);
#pragma unroll
        for (int r = 0; r < 4; r++) {
            float a = A[(rq + 16*r)*PB + k];
            u64t a2 = pk2(a, a);
            acc[r][0] = ffma2(a2, b0, acc[r][0]);
            acc[r][1] = ffma2(a2, b1, acc[r][1]);
        }
    }
}
__device__ __noinline__ void mm64_smem(const float* __restrict__ A,
                                       const float* __restrict__ B,
                                       float* __restrict__ C, int tid) {
    int cq = tid & 15, rq = tid >> 4;
    u64t acc[4][2] = {};
    mm64_core(A, B, rq, cq, acc);
#pragma unroll
    for (int r = 0; r < 4; r++) {
        *(u64t*)(C + (rq+16*r)*PB + 2*cq)      = acc[r][0];
        *(u64t*)(C + (rq+16*r)*PB + 2*cq + 32) = acc[r][1];
    }
}
// write acc with transform Ct = aI - bS*C (per-thread tile)
__device__ __forceinline__ void tr_write(float* Ct, int rq, int cq, float aI, float bS,
                                         const u64t acc[4][2]) {
    int j0 = 2*cq, j2 = 2*cq + 32;
#pragma unroll
    for (int r = 0; r < 4; r++) {
        int row = rq + 16*r;
        float v0, v1, v2, v3;
        asm("mov.b64 {%0, %1}, %2;" : "=f"(v0), "=f"(v1) : "l"(acc[r][0]));
        asm("mov.b64 {%0, %1}, %2;" : "=f"(v2), "=f"(v3) : "l"(acc[r][1]));
        float t0 = (row == j0   ? aI : 0.f) - bS*v0;
        float t1 = (row == j0+1 ? aI : 0.f) - bS*v1;
        float t2 = (row == j2   ? aI : 0.f) - bS*v2;
        float t3 = (row == j2+1 ? aI : 0.f) - bS*v3;
        *(u64t*)(Ct + row*PB + j0) = pk2(t0, t1);
        *(u64t*)(Ct + row*PB + j2) = pk2(t2, t3);
    }
}
__device__ __forceinline__ void raw_write(float* C, int rq, int cq, const u64t acc[4][2]) {
#pragma unroll
    for (int r = 0; r < 4; r++) {
        int row = rq + 16*r;
        *(u64t*)(C + row*PB + 2*cq)      = acc[r][0];
        *(u64t*)(C + row*PB + 2*cq + 32) = acc[r][1];
    }
}

// ---------------- pooling ----------------
__global__ void __launch_bounds__(256) pool_kernel(const float* __restrict__ Q,
                                                   const float* __restrict__ K) {
    int bh = blockIdx.x >> 6, lm = blockIdx.x & 63;
    int d = threadIdx.x & 63, rg = threadIdx.x >> 6;
    const float* qb = Q + ((size_t)bh*SQ + lm*64)*64 + d;
    const float* kb = K + ((size_t)bh*SQ + lm*64)*64 + d;
    float sq = 0.f, sk = 0.f;
    for (int r = rg; r < 64; r += 4) { sq += qb[(size_t)r*64]; sk += kb[(size_t)r*64]; }
    __shared__ float shq[256], shk[256];
    shq[threadIdx.x] = sq; shk[threadIdx.x] = sk;
    __syncthreads();
    if (rg == 0) {
        float q = (shq[d] + shq[64+d] + shq[128+d] + shq[192+d]) * (1.0f/512.0f);
        float k = (shk[d] + shk[64+d] + shk[128+d] + shk[192+d]) * (1.0f/64.0f);
        g_Qlm [bh*4096 + lm*64 + d] = q;
        g_Klm [bh*4096 + lm*64 + d] = k;
        g_KlmT[bh*4096 + d*64 + lm] = k;
    }
}

// ---------------- Newton-Schulz body: 4 buffers, exact fp32 trajectory ----------------
__device__ void newton_body(float* sm, int bh) {
    float* A = sm;
    float* X = sm + 1*64*PB;
    float* Y = sm + 2*64*PB;
    float* Z = sm + 3*64*PB;
    __shared__ float nsred[256], nsrow[64], nscol[64], nscale[1];
    int tid = threadIdx.x;
    int cq = tid & 15, rq = tid >> 4;

    for (int idx = tid; idx < 4096; idx += 256) {
        int i = idx >> 6, k = idx & 63;
        Y[i*PB + k] = g_Qlm[bh*4096 + idx];
        Z[i*PB + k] = g_KlmT[bh*4096 + idx];
    }
    __syncthreads();
    mm64_smem(Y, Z, A, tid);
    __syncthreads();
    {
        int q = tid & 3, r = tid >> 2;
        float* Lr = A + r*PB + q*16;
        float mt = Lr[0];
#pragma unroll
        for (int c = 1; c < 16; c++) mt = fmaxf(mt, Lr[c]);
        nsred[tid] = mt; __syncthreads();
        float m = fmaxf(fmaxf(nsred[r*4], nsred[r*4+1]), fmaxf(nsred[r*4+2], nsred[r*4+3]));
        float ps = 0.f;
#pragma unroll
        for (int c = 0; c < 16; c++) { float e = __expf(Lr[c] - m); Lr[c] = e; ps += e; }
        __syncthreads();
        nsred[tid] = ps; __syncthreads();
        float inv = 1.0f / (nsred[r*4] + nsred[r*4+1] + nsred[r*4+2] + nsred[r*4+3]);
#pragma unroll
        for (int c = 0; c < 16; c++) Lr[c] *= inv;
    }
    __syncthreads();
    if (tid < 64)       { float s = 0.f; for (int j = 0; j < 64; j++) s += A[tid*PB + j]; nsrow[tid] = s; }
    else if (tid < 128) { int c = tid - 64; float s = 0.f; for (int i = 0; i < 64; i++) s += A[i*PB + c]; nscol[c] = s; }
    __syncthreads();
    if (tid == 0) {
        float mr = nsrow[0], mc = nscol[0];
        for (int i = 1; i < 64; i++) { mr = fmaxf(mr, nsrow[i]); mc = fmaxf(mc, nscol[i]); }
        nscale[0] = 1.0f / (mr * mc);
    }
    __syncthreads();
    float sc = nscale[0];
    for (int idx = tid; idx < 4096; idx += 256) {
        int i = idx >> 6, j = idx & 63;
        X[j*PB + i] = A[i*PB + j] * sc;
    }
    __syncthreads();

    float *Vb = X, *F1 = Y, *F2 = Z;
#pragma unroll 1
    for (int it = 0; it < 6; it++) {
        {   // mm1: acc = A@Vb -> P raw into F1, T1=7I-P into F2 (both free)
            u64t acc[4][2] = {};
            mm64_core(A, Vb, rq, cq, acc);
            raw_write(F1, rq, cq, acc);
            tr_write(F2, rq, cq, 7.0f, 1.0f, acc);
        }
        __syncthreads();
        {   // mm2: acc = F1@F2 (P@T1); T2 = 15I-acc overwrites F2 (input)
            u64t acc[4][2] = {};
            mm64_core(F1, F2, rq, cq, acc);
            __syncthreads();
            tr_write(F2, rq, cq, 15.0f, 1.0f, acc);
        }
        __syncthreads();
        {   // mm3: acc = F1@F2 (P@T2); T3 = 3.25I-0.25acc overwrites F1 (input)
            u64t acc[4][2] = {};
            mm64_core(F1, F2, rq, cq, acc);
            __syncthreads();
            tr_write(F1, rq, cq, 3.25f, 0.25f, acc);
        }
        __syncthreads();
        {   // mm4: acc = Vb@F1 (Vb@T3) -> Vnew into F2 (T2 dead; not an input here)
            u64t acc[4][2] = {};
            mm64_core(Vb, F1, rq, cq, acc);
            raw_write(F2, rq, cq, acc);
        }
        __syncthreads();
        float* nv = F2; F2 = F1; F1 = Vb; Vb = nv;
    }
    for (int idx = tid; idx < 4096; idx += 256) {
        int i = idx >> 6, j = idx & 63;
        g_Inv[bh*4096 + idx] = Vb[i*PB + j];
    }
}

// ---------------- kc body: 8 warps share one tile (M x s/d split) ----------------
__device__ void kc_body(const float* __restrict__ K, const float* __restrict__ V,
                        u32* sm, int sp, int bh) {
    u32* Qlh = sm;
    u32* Qll = sm + 64*PW;
    u32* KPh = sm + 2*64*PW;   // K tile, later P
    u32* KPl = sm + 3*64*PW;
    u32* Vh  = sm + 4*64*PW;
    u32* Vl  = sm + 5*64*PW;
    __shared__ float srs[8][16];
    int tid = threadIdx.x, lane = tid & 31, wid = tid >> 5;
    int g = lane >> 2, t = lane & 3;
    int wd = wid & 3, half = wid >> 2;
    int base = wd*16, nb = half*32, co = half*16;

    stage_k(Qlh, Qll, g_Qlm + bh*4096, 64, tid, 256, 1.0f);  // already *0.125

    float acc[4][4] = {};
    float rs0 = 0.f, rs1 = 0.f;
    __syncthreads();

#pragma unroll 1
    for (int it = 0; it < 4; it++) {
        int s0 = sp*256 + it*64;
        stage_k(KPh, KPl, K + ((size_t)bh*SQ + s0)*64, 64, tid, 256, 1.0f);
        stage_v(Vh, Vl, V + ((size_t)bh*SQ + s0)*64, tid, 256);
        __syncthreads();

        float c[4][4] = {};
        wg16x32(Qlh, Qll, base, KPh, KPl, nb, lane, c);   // logits[lm 16][s 32]

#pragma unroll
        for (int n = 0; n < 4; n++) {
            c[n][0] = __expf(c[n][0]); c[n][1] = __expf(c[n][1]);
            c[n][2] = __expf(c[n][2]); c[n][3] = __expf(c[n][3]);
            rs0 += c[n][0] + c[n][1];
            rs1 += c[n][2] + c[n][3];
        }
        __syncthreads();                      // all K reads done
        write_P32(KPh, KPl, base, co, g, t, c);
        __syncthreads();                      // P complete (cross-warp)
        wg16x32(KPh, KPl, base, Vh, Vl, nb, lane, acc);   // acc += P@V (d half)
        __syncthreads();                      // before restage
    }

    rs0 += __shfl_xor_sync(0xffffffffu, rs0, 1);
    rs0 += __shfl_xor_sync(0xffffffffu, rs0, 2);
    rs1 += __shfl_xor_sync(0xffffffffu, rs1, 1);
    rs1 += __shfl_xor_sync(0xffffffffu, rs1, 2);
    if (t == 0) { srs[wid][g] = rs0; srs[wid][g + 8] = rs1; }

    size_t pb = ((size_t)sp*BHN + bh)*4096;
    int r0 = base + g;
#pragma unroll
    for (int nt = 0; nt < 4; nt++) {
        int col = nb + 8*nt + 2*t;
        *(float2*)(g_pacc + pb + r0*64 + col)     = make_float2(acc[nt][0], acc[nt][1]);
        *(float2*)(g_pacc + pb + (r0+8)*64 + col) = make_float2(acc[nt][2], acc[nt][3]);
    }
    __syncthreads();
    if (half == 0 && lane < 16) {
        float tot = srs[wid][lane] + srs[wid + 4][lane];
        g_psum[(sp*BHN + bh)*64 + base + lane] = tot;
    }
}

__global__ void __launch_bounds__(256, 3) mega_kernel(const float* __restrict__ K,
                                                      const float* __restrict__ V) {
    extern __shared__ __align__(16) u32 smg[];
    if (blockIdx.x < 64) newton_body((float*)smg, blockIdx.x);
    else { int id = blockIdx.x - 64; kc_body(K, V, smg, id & (NS2-1), id >> 4); }
}

// ---------------- reduce splits -> F, W = Inv@F, store W^T ----------------
__global__ void __launch_bounds__(256) reduce_winv_kernel() {
    extern __shared__ __align__(16) float smr[];
    float* Fs = smr;
    float* Iv = smr + 64*PB;
    int bh = blockIdx.x, tid = threadIdx.x;

    for (int idx = tid; idx < 4096; idx += 256)
        Iv[(idx>>6)*PB + (idx&63)] = g_Inv[bh*4096 + idx];

    int d = tid & 63, ig = tid >> 6;
    for (int i = ig; i < 64; i += 4) {
        float tot = 0.f;
#pragma unroll
        for (int s = 0; s < NS2; s++) tot += g_psum[(s*BHN+bh)*64 + i];
        float v = 0.f;
#pragma unroll
        for (int s = 0; s < NS2; s++)
            v += g_pacc[((size_t)s*BHN+bh)*4096 + i*64 + d];
        Fs[i*PB + d] = v / tot;
    }
    __syncthreads();
    int cq = tid & 15, rq = tid >> 4;
    u64t acc[4][2] = {};
    mm64_core(Iv, Fs, rq, cq, acc);
    float* wt = g_WT + (size_t)bh*4096;
#pragma unroll
    for (int rr = 0; rr < 4; rr++) {
        int row = rq + 16*rr;
        float v0, v1, v2, v3;
        asm("mov.b64 {%0, %1}, %2;" : "=f"(v0), "=f"(v1) : "l"(acc[rr][0]));
        asm("mov.b64 {%0, %1}, %2;" : "=f"(v2), "=f"(v3) : "l"(acc[rr][1]));
        wt[(2*cq)*64    + row] = v0;
        wt[(2*cq+1)*64  + row] = v1;
        wt[(2*cq+32)*64 + row] = v2;
        wt[(2*cq+33)*64 + row] = v3;
    }
}

// ---------------- kd: 8 warps, M=16/warp, 2 tiles per CTA ----------------
__global__ void __launch_bounds__(256, 3) kd_bf(const float* __restrict__ Q,
                                                float* __restrict__ X) {
    extern __shared__ __align__(16) u32 smk[];
    u32* Qh = smk;
    u32* Ql = Qh + 128*PW;
    u32* Kh = Ql + 128*PW;
    u32* Kl = Kh + 64*PW;
    u32* Wh = Kl + 64*PW;
    u32* Wl = Wh + 64*PW;
    int tid = threadIdx.x, lane = tid & 31, wid = tid >> 5;
    int g = lane >> 2, t = lane & 3;
    int bh = blockIdx.y;

    stage_k(Kh, Kl, g_Klm + (size_t)bh*4096, 64, tid, 256, 1.0f);
    stage_k(Wh, Wl, g_WT  + (size_t)bh*4096, 64, tid, 256, 1.0f);

    int base = wid*16;
    int r0 = base + g;

#pragma unroll 1
    for (int t2 = 0; t2 < 2; t2++) {
        int tile = blockIdx.x*2 + t2;
        if (t2) __syncthreads();
        stage_k(Qh, Ql, Q + ((size_t)bh*SQ + tile*128)*64, 128, tid, 256, 0.125f);
        __syncthreads();

        float c[8][4];
#pragma unroll
        for (int n = 0; n < 8; n++) { c[n][0]=0.f; c[n][1]=0.f; c[n][2]=0.f; c[n][3]=0.f; }
        wgemm16(Qh, Ql, base, Kh, Kl, lane, c);   // logits [tok][lm]

        float rs0 = 0.f, rs1 = 0.f;
#pragma unroll
        for (int n = 0; n < 8; n++) {
            c[n][0] = __expf(c[n][0]); c[n][1] = __expf(c[n][1]);
            c[n][2] = __expf(c[n][2]); c[n][3] = __expf(c[n][3]);
            rs0 += c[n][0] + c[n][1];
            rs1 += c[n][2] + c[n][3];
        }
        rs0 += __shfl_xor_sync(0xffffffffu, rs0, 1);
        rs0 += __shfl_xor_sync(0xffffffffu, rs0, 2);
        rs1 += __shfl_xor_sync(0xffffffffu, rs1, 1);
        rs1 += __shfl_xor_sync(0xffffffffu, rs1, 2);
        float rinv0 = 1.0f / rs0, rinv1 = 1.0f / rs1;

        write_P16(Qh, Ql, base, g, t, c);
        __syncwarp();

#pragma unroll
        for (int n = 0; n < 8; n++) { c[n][0]=0.f; c[n][1]=0.f; c[n][2]=0.f; c[n][3]=0.f; }
        wgemm16(Qh, Ql, base, Wh, Wl, lane, c);   // X~ = P @ W

        float* x0 = X + ((size_t)bh*SQ + tile*128)*64;
#pragma unroll
        for (int nt = 0; nt < 8; nt++) {
            int col = 8*nt + 2*t;
            *(float2*)(x0 + r0*64 + col)     = make_float2(c[nt][0]*rinv0, c[nt][1]*rinv0);
            *(float2*)(x0 + (r0+8)*64 + col) = make_float2(c[nt][2]*rinv1, c[nt][3]*rinv1);
        }
    }
}

// ---------------- launcher ----------------
extern "C" void kernel_launch(void* const* d_in, const int* in_sizes, int n_in,
                              void* d_out, int out_size) {
    (void)in_sizes; (void)n_in; (void)out_size;
    const float* Q = (const float*)d_in[0];
    const float* K = (const float*)d_in[1];
    const float* V = (const float*)d_in[2];
    float* X = (float*)d_out;

    const int SMEM_MEGA = 4*64*PB*4;    // 69632 (newton); kc uses 55296 -> 3 CTAs/SM
    const int SMEM_RW   = 2*64*PB*4;    // 34816
    const int SMEM_KD   = 512*PW*4;     // 73728 -> 3 CTAs/SM
    cudaFuncSetAttribute(mega_kernel,        cudaFuncAttributeMaxDynamicSharedMemorySize, SMEM_MEGA);
    cudaFuncSetAttribute(reduce_winv_kernel, cudaFuncAttributeMaxDynamicSharedMemorySize, SMEM_RW);
    cudaFuncSetAttribute(kd_bf,              cudaFuncAttributeMaxDynamicSharedMemorySize, SMEM_KD);

    pool_kernel<<<BHN*64, 256>>>(Q, K);
    mega_kernel<<<64 + NS2*BHN, 256, SMEM_MEGA>>>(K, V);
    reduce_winv_kernel<<<BHN, 256, SMEM_RW>>>();
    kd_bf<<<dim3(16, BHN), 256, SMEM_KD>>>(Q, X);
}